// round 8
// baseline (speedup 1.0000x reference)
#include <cuda_runtime.h>
#include <cuda_bf16.h>
#include <cuda_fp16.h>
#include <cstdint>
#include <math.h>

// ---------------- problem constants ----------------------------------------
#define N_NODES 100000
#define N_EDGES 1600000
#define F_IN    256
#define F_HID   256
#define F_OUT   128
#define K_TOT   256          // K dim for both GEMMs

#define SCAN_CHUNK  1024
#define SCAN_BLOCKS ((N_NODES + SCAN_CHUNK - 1) / SCAN_CHUNK)   // 98

// ---------------- device scratch (static, no allocations) ------------------
__device__ int   g_deg[N_NODES];
__device__ float g_dinv[N_NODES];
__device__ int   g_rowstart[N_NODES + 1];
__device__ int   g_cursor[N_NODES];
__device__ int   g_partial[SCAN_BLOCKS];
__device__ int   g_csr_src[N_EDGES];
__device__ float g_csr_w[N_EDGES];

__device__ __nv_bfloat16 g_w1t_hi[F_HID * K_TOT];     // [256][256] = W1^T
__device__ __nv_bfloat16 g_w1t_lo[F_HID * K_TOT];
__device__ __nv_bfloat16 g_w2t_hi[F_OUT * K_TOT];     // [128][256] = W2^T
__device__ __nv_bfloat16 g_w2t_lo[F_OUT * K_TOT];
__device__ __half g_h1[(size_t)N_NODES * F_HID];       // x @ W1 (fp16)
__device__ float  g_a1[(size_t)N_NODES * F_HID];       // relu(agg(h1)+b1) fp32
__device__ __half g_h2[(size_t)N_NODES * F_OUT];       // a1 @ W2 (fp16)

// ---------------- CSR construction -----------------------------------------

__global__ void init_kernel() {
    int i = blockIdx.x * blockDim.x + threadIdx.x;
    if (i < N_NODES) { g_deg[i] = 1; g_cursor[i] = 0; }
}

__global__ void count_kernel(const int* __restrict__ dst, int E) {
    int e = blockIdx.x * blockDim.x + threadIdx.x;
    if (e < E) atomicAdd(&g_deg[dst[e]], 1);
}

__global__ void dinv_kernel() {
    int i = blockIdx.x * blockDim.x + threadIdx.x;
    if (i < N_NODES) g_dinv[i] = rsqrtf((float)g_deg[i]);
}

__global__ __launch_bounds__(256) void scan_partial_kernel() {
    __shared__ int red[256];
    const int base = blockIdx.x * SCAN_CHUNK;
    int s = 0;
    for (int j = threadIdx.x; j < SCAN_CHUNK; j += 256) {
        int idx = base + j;
        if (idx < N_NODES) s += g_deg[idx] - 1;
    }
    red[threadIdx.x] = s;
    __syncthreads();
    #pragma unroll
    for (int off = 128; off > 0; off >>= 1) {
        if (threadIdx.x < off) red[threadIdx.x] += red[threadIdx.x + off];
        __syncthreads();
    }
    if (threadIdx.x == 0) g_partial[blockIdx.x] = red[0];
}

__global__ void scan_top_kernel() {
    __shared__ int sh[SCAN_BLOCKS];
    for (int i = threadIdx.x; i < SCAN_BLOCKS; i += blockDim.x) sh[i] = g_partial[i];
    __syncthreads();
    if (threadIdx.x == 0) {
        int run = 0;
        for (int i = 0; i < SCAN_BLOCKS; i++) { int v = sh[i]; sh[i] = run; run += v; }
        g_rowstart[N_NODES] = run;
    }
    __syncthreads();
    for (int i = threadIdx.x; i < SCAN_BLOCKS; i += blockDim.x) g_partial[i] = sh[i];
}

__global__ __launch_bounds__(256) void scan_final_kernel() {
    __shared__ int sh[256];
    const int t = threadIdx.x;
    const int idx0 = blockIdx.x * SCAN_CHUNK + t * 4;
    int v[4]; int s = 0;
    #pragma unroll
    for (int j = 0; j < 4; j++) {
        int idx = idx0 + j;
        int d = (idx < N_NODES) ? (g_deg[idx] - 1) : 0;
        v[j] = s; s += d;
    }
    sh[t] = s;
    __syncthreads();
    #pragma unroll
    for (int off = 1; off < 256; off <<= 1) {
        int val = (t >= off) ? sh[t - off] : 0;
        __syncthreads();
        sh[t] += val;
        __syncthreads();
    }
    int excl = ((t == 0) ? 0 : sh[t - 1]) + g_partial[blockIdx.x];
    #pragma unroll
    for (int j = 0; j < 4; j++) {
        int idx = idx0 + j;
        if (idx < N_NODES) g_rowstart[idx] = excl + v[j];
    }
}

__global__ void fill_kernel(const int* __restrict__ src,
                            const int* __restrict__ dst, int E) {
    int e = blockIdx.x * blockDim.x + threadIdx.x;
    if (e < E) {
        int d = dst[e];
        int s = src[e];
        int pos = atomicAdd(&g_cursor[d], 1);
        int idx = g_rowstart[d] + pos;
        g_csr_src[idx] = s;
        g_csr_w[idx]   = g_dinv[s] * g_dinv[d];
    }
}

// ---------------- weight conversion: W [K][N] -> WT hi/lo [N][K] ------------

__global__ void convert_w_kernel(const float* __restrict__ W,
                                 __nv_bfloat16* __restrict__ hi,
                                 __nv_bfloat16* __restrict__ lo,
                                 int K, int N) {
    int i = blockIdx.x * blockDim.x + threadIdx.x;
    if (i >= N * K) return;
    int nrow = i / K;
    int k = i - nrow * K;
    float v = W[(size_t)k * N + nrow];
    __nv_bfloat16 h = __float2bfloat16(v);
    hi[i] = h;
    lo[i] = __float2bfloat16(v - __bfloat162float(h));
}

// ---------------- mma.sync bf16x3 GEMM --------------------------------------
// C[M rows, 128-col slice](fp16) = A[M,256](fp32) @ B^T, B as bf16 (hi,lo).
// A split to bf16 hi/lo in registers while staging to smem.
// CTA tile 128x128, 16 warps (4 m x 4 n), warp tile 32x32, 512 threads.

#define LDSK 40   // bf16 elements per smem row (32 data + 8 pad); 80B, 16B-mult

#define MMA_BF16(d, a, b) \
    asm volatile("mma.sync.aligned.m16n8k16.row.col.f32.bf16.bf16.f32 " \
        "{%0,%1,%2,%3}, {%4,%5,%6,%7}, {%8,%9}, {%0,%1,%2,%3};" \
        : "+f"((d)[0]), "+f"((d)[1]), "+f"((d)[2]), "+f"((d)[3]) \
        : "r"((a)[0]), "r"((a)[1]), "r"((a)[2]), "r"((a)[3]), \
          "r"((b)[0]), "r"((b)[1]))

__global__ __launch_bounds__(512)
void mma_gemm_kernel(const float* __restrict__ A,
                     const __nv_bfloat16* __restrict__ Bhi,
                     const __nv_bfloat16* __restrict__ Blo,
                     __half* __restrict__ C, int M, int ldc) {
    __shared__ __align__(16) __nv_bfloat16 sAh[128 * LDSK];
    __shared__ __align__(16) __nv_bfloat16 sAl[128 * LDSK];
    __shared__ __align__(16) __nv_bfloat16 sBh[128 * LDSK];
    __shared__ __align__(16) __nv_bfloat16 sBl[128 * LDSK];

    const int tid  = threadIdx.x;
    const int wid  = tid >> 5;
    const int lane = tid & 31;
    const int warp_m = wid & 3;        // 0..3 -> m offset 32*warp_m
    const int warp_n = wid >> 2;       // 0..3 -> n offset 32*warp_n
    const int block_row = blockIdx.x * 128;
    const int n0 = blockIdx.y * 128;

    const int g = lane >> 2;           // 0..7
    const int q = lane & 3;            // 0..3

    float acc[8][4];
    #pragma unroll
    for (int i = 0; i < 8; i++)
        #pragma unroll
        for (int j = 0; j < 4; j++) acc[i][j] = 0.0f;

    for (int c = 0; c < 8; c++) {
        const int k0 = c * 32;

        // A chunk: 128 rows x 8 float4 = 1024 float4; split to hi/lo in regs.
        #pragma unroll
        for (int t = tid; t < 1024; t += 512) {
            const int row = t >> 3;
            const int u   = t & 7;
            const int grow = block_row + row;
            float4 v = make_float4(0.f, 0.f, 0.f, 0.f);
            if (grow < M)
                v = *reinterpret_cast<const float4*>(
                    A + (size_t)grow * K_TOT + k0 + u * 4);
            __nv_bfloat16 hx = __float2bfloat16(v.x);
            __nv_bfloat16 hy = __float2bfloat16(v.y);
            __nv_bfloat16 hz = __float2bfloat16(v.z);
            __nv_bfloat16 hw = __float2bfloat16(v.w);
            __nv_bfloat162 h01 = __halves2bfloat162(hx, hy);
            __nv_bfloat162 h23 = __halves2bfloat162(hz, hw);
            __nv_bfloat162 l01 = __halves2bfloat162(
                __float2bfloat16(v.x - __bfloat162float(hx)),
                __float2bfloat16(v.y - __bfloat162float(hy)));
            __nv_bfloat162 l23 = __halves2bfloat162(
                __float2bfloat16(v.z - __bfloat162float(hz)),
                __float2bfloat16(v.w - __bfloat162float(hw)));
            __nv_bfloat162* dh = reinterpret_cast<__nv_bfloat162*>(
                sAh + row * LDSK + u * 4);
            __nv_bfloat162* dl = reinterpret_cast<__nv_bfloat162*>(
                sAl + row * LDSK + u * 4);
            dh[0] = h01; dh[1] = h23;
            dl[0] = l01; dl[1] = l23;
        }
        // B chunk: hi+lo, 128 rows x 4 uint4 each => 1024 uint4
        #pragma unroll
        for (int t = tid; t < 1024; t += 512) {
            const int arr = t >> 9;
            const int idx = t & 511;
            const int row = idx >> 2;
            const int u   = idx & 3;
            const __nv_bfloat16* src = arr ? Blo : Bhi;
            uint4 v = *reinterpret_cast<const uint4*>(
                src + (size_t)(n0 + row) * K_TOT + k0 + u * 8);
            __nv_bfloat16* dst = (arr ? sBl : sBh) + row * LDSK + u * 8;
            *reinterpret_cast<uint4*>(dst) = v;
        }
        __syncthreads();

        #pragma unroll
        for (int kk = 0; kk < 2; kk++) {
            const int kb = kk * 16;
            uint32_t Ah[2][4], Al[2][4];
            #pragma unroll
            for (int t = 0; t < 2; t++) {
                const int r0 = (warp_m * 32 + t * 16 + g) * LDSK + kb + q * 2;
                const int r1 = r0 + 8 * LDSK;
                Ah[t][0] = *reinterpret_cast<const uint32_t*>(&sAh[r0]);
                Ah[t][1] = *reinterpret_cast<const uint32_t*>(&sAh[r1]);
                Ah[t][2] = *reinterpret_cast<const uint32_t*>(&sAh[r0 + 8]);
                Ah[t][3] = *reinterpret_cast<const uint32_t*>(&sAh[r1 + 8]);
                Al[t][0] = *reinterpret_cast<const uint32_t*>(&sAl[r0]);
                Al[t][1] = *reinterpret_cast<const uint32_t*>(&sAl[r1]);
                Al[t][2] = *reinterpret_cast<const uint32_t*>(&sAl[r0 + 8]);
                Al[t][3] = *reinterpret_cast<const uint32_t*>(&sAl[r1 + 8]);
            }
            uint32_t Bh[4][2], Bl[4][2];
            #pragma unroll
            for (int j = 0; j < 4; j++) {
                const int rb = (warp_n * 32 + j * 8 + g) * LDSK + kb + q * 2;
                Bh[j][0] = *reinterpret_cast<const uint32_t*>(&sBh[rb]);
                Bh[j][1] = *reinterpret_cast<const uint32_t*>(&sBh[rb + 8]);
                Bl[j][0] = *reinterpret_cast<const uint32_t*>(&sBl[rb]);
                Bl[j][1] = *reinterpret_cast<const uint32_t*>(&sBl[rb + 8]);
            }
            #pragma unroll
            for (int t = 0; t < 2; t++)
                #pragma unroll
                for (int j = 0; j < 4; j++) {
                    float* d = acc[t * 4 + j];
                    MMA_BF16(d, Ah[t], Bh[j]);   // hi*hi
                    MMA_BF16(d, Ah[t], Bl[j]);   // hi*lo
                    MMA_BF16(d, Al[t], Bh[j]);   // lo*hi
                }
        }
        __syncthreads();
    }

    // store fp16: c0,c1 -> row g; c2,c3 -> row g+8; cols 2q,2q+1
    #pragma unroll
    for (int t = 0; t < 2; t++) {
        const int row0 = block_row + warp_m * 32 + t * 16 + g;
        #pragma unroll
        for (int j = 0; j < 4; j++) {
            const int col = n0 + warp_n * 32 + j * 8 + q * 2;
            const float* d = acc[t * 4 + j];
            if (row0 < M)
                *reinterpret_cast<__half2*>(C + (size_t)row0 * ldc + col) =
                    __floats2half2_rn(d[0], d[1]);
            if (row0 + 8 < M)
                *reinterpret_cast<__half2*>(C + (size_t)(row0 + 8) * ldc + col) =
                    __floats2half2_rn(d[2], d[3]);
        }
    }
}

// ---------------- sparse aggregation (fp16 gather, fp32 accumulate) --------
// Out[i] = relu( bias + dinv[i]^2 * H[i] + sum_e w_e * H[src_e] )
// F/8 lanes per node; uint4 = 8 halves per lane; 8-edge MLP pipeline.
template <int F>
__global__ __launch_bounds__(256)
void agg_kernel(const __half* __restrict__ H, const float* __restrict__ bias,
                float* __restrict__ Out) {
    const int lanes = F / 8;                 // 32 (F=256) or 16 (F=128)
    const int tid = threadIdx.x;
    const int node = blockIdx.x * (256 / lanes) + tid / lanes;
    if (node >= N_NODES) return;
    const int f = (tid % lanes) * 8;

    const float di = g_dinv[node];
    const float w0 = di * di;

    float acc0[8], acc1[8], acc2[8], acc3[8];
    {
        uint4 hv = *reinterpret_cast<const uint4*>(H + (size_t)node * F + f);
        const __half2* hp = reinterpret_cast<const __half2*>(&hv);
        #pragma unroll
        for (int j = 0; j < 4; j++) {
            float2 v = __half22float2(hp[j]);
            acc0[j * 2 + 0] = fmaf(w0, v.x, bias[f + j * 2 + 0]);
            acc0[j * 2 + 1] = fmaf(w0, v.y, bias[f + j * 2 + 1]);
        }
    }
    #pragma unroll
    for (int j = 0; j < 8; j++) { acc1[j] = 0.f; acc2[j] = 0.f; acc3[j] = 0.f; }

    int e = g_rowstart[node];
    const int end = g_rowstart[node + 1];

    // 8-edge unrolled main loop: issue all 8 gathers before consuming.
    for (; e + 8 <= end; e += 8) {
        int   s[8];
        float w[8];
        #pragma unroll
        for (int i = 0; i < 8; i++) {
            s[i] = __ldg(&g_csr_src[e + i]);
            w[i] = __ldg(&g_csr_w[e + i]);
        }
        uint4 v[8];
        #pragma unroll
        for (int i = 0; i < 8; i++)
            v[i] = *reinterpret_cast<const uint4*>(H + (size_t)s[i] * F + f);
        #pragma unroll
        for (int i = 0; i < 8; i++) {
            const __half2* p = reinterpret_cast<const __half2*>(&v[i]);
            float* a = (i & 3) == 0 ? acc0 : (i & 3) == 1 ? acc1
                      : (i & 3) == 2 ? acc2 : acc3;
            #pragma unroll
            for (int j = 0; j < 4; j++) {
                float2 fv = __half22float2(p[j]);
                a[j*2+0] = fmaf(w[i], fv.x, a[j*2+0]);
                a[j*2+1] = fmaf(w[i], fv.y, a[j*2+1]);
            }
        }
    }
    // 4-edge mid loop
    for (; e + 4 <= end; e += 4) {
        int   s[4];
        float w[4];
        #pragma unroll
        for (int i = 0; i < 4; i++) {
            s[i] = __ldg(&g_csr_src[e + i]);
            w[i] = __ldg(&g_csr_w[e + i]);
        }
        uint4 v[4];
        #pragma unroll
        for (int i = 0; i < 4; i++)
            v[i] = *reinterpret_cast<const uint4*>(H + (size_t)s[i] * F + f);
        #pragma unroll
        for (int i = 0; i < 4; i++) {
            const __half2* p = reinterpret_cast<const __half2*>(&v[i]);
            float* a = i == 0 ? acc0 : i == 1 ? acc1 : i == 2 ? acc2 : acc3;
            #pragma unroll
            for (int j = 0; j < 4; j++) {
                float2 fv = __half22float2(p[j]);
                a[j*2+0] = fmaf(w[i], fv.x, a[j*2+0]);
                a[j*2+1] = fmaf(w[i], fv.y, a[j*2+1]);
            }
        }
    }
    // scalar tail
    for (; e < end; e++) {
        int   s = __ldg(&g_csr_src[e]);
        float w = __ldg(&g_csr_w[e]);
        uint4 v = *reinterpret_cast<const uint4*>(H + (size_t)s * F + f);
        const __half2* p = reinterpret_cast<const __half2*>(&v);
        #pragma unroll
        for (int j = 0; j < 4; j++) {
            float2 fv = __half22float2(p[j]);
            acc0[j*2+0] = fmaf(w, fv.x, acc0[j*2+0]);
            acc0[j*2+1] = fmaf(w, fv.y, acc0[j*2+1]);
        }
    }

    float4 r0, r1;
    r0.x = fmaxf((acc0[0] + acc1[0]) + (acc2[0] + acc3[0]), 0.0f);
    r0.y = fmaxf((acc0[1] + acc1[1]) + (acc2[1] + acc3[1]), 0.0f);
    r0.z = fmaxf((acc0[2] + acc1[2]) + (acc2[2] + acc3[2]), 0.0f);
    r0.w = fmaxf((acc0[3] + acc1[3]) + (acc2[3] + acc3[3]), 0.0f);
    r1.x = fmaxf((acc0[4] + acc1[4]) + (acc2[4] + acc3[4]), 0.0f);
    r1.y = fmaxf((acc0[5] + acc1[5]) + (acc2[5] + acc3[5]), 0.0f);
    r1.z = fmaxf((acc0[6] + acc1[6]) + (acc2[6] + acc3[6]), 0.0f);
    r1.w = fmaxf((acc0[7] + acc1[7]) + (acc2[7] + acc3[7]), 0.0f);
    float* dst = Out + (size_t)node * F + f;
    *reinterpret_cast<float4*>(dst)     = r0;
    *reinterpret_cast<float4*>(dst + 4) = r1;
}

// ---------------- launcher ---------------------------------------------------

extern "C" void kernel_launch(void* const* d_in, const int* in_sizes, int n_in,
                              void* d_out, int out_size) {
    const float* x  = (const float*)d_in[0];
    const int*   ei = (const int*)d_in[1];
    const float* W1 = (const float*)d_in[2];
    const float* b1 = (const float*)d_in[3];
    const float* W2 = (const float*)d_in[4];
    const float* b2 = (const float*)d_in[5];
    float* out = (float*)d_out;

    const int E = in_sizes[1] / 2;
    const int* src = ei;
    const int* dst = ei + E;

    __half *h1p = nullptr, *h2p = nullptr;
    float  *a1p = nullptr;
    __nv_bfloat16 *w1thi = nullptr, *w1tlo = nullptr;
    __nv_bfloat16 *w2thi = nullptr, *w2tlo = nullptr;
    cudaGetSymbolAddress((void**)&h1p, g_h1);
    cudaGetSymbolAddress((void**)&h2p, g_h2);
    cudaGetSymbolAddress((void**)&a1p, g_a1);
    cudaGetSymbolAddress((void**)&w1thi, g_w1t_hi);
    cudaGetSymbolAddress((void**)&w1tlo, g_w1t_lo);
    cudaGetSymbolAddress((void**)&w2thi, g_w2t_hi);
    cudaGetSymbolAddress((void**)&w2tlo, g_w2t_lo);

    const int TB = 256;
    // CSR build
    init_kernel<<<(N_NODES + TB - 1) / TB, TB>>>();
    count_kernel<<<(E + TB - 1) / TB, TB>>>(dst, E);
    dinv_kernel<<<(N_NODES + TB - 1) / TB, TB>>>();
    scan_partial_kernel<<<SCAN_BLOCKS, 256>>>();
    scan_top_kernel<<<1, 128>>>();
    scan_final_kernel<<<SCAN_BLOCKS, 256>>>();
    fill_kernel<<<(E + TB - 1) / TB, TB>>>(src, dst, E);

    // weight conversions (tiny)
    convert_w_kernel<<<(F_HID * K_TOT + TB - 1) / TB, TB>>>(W1, w1thi, w1tlo, K_TOT, F_HID);
    convert_w_kernel<<<(F_OUT * K_TOT + TB - 1) / TB, TB>>>(W2, w2thi, w2tlo, K_TOT, F_OUT);

    const int MT = (N_NODES + 127) / 128;   // 782

    // layer 1: h1 = x @ W1 (fp16 out), a1 = relu(agg(h1)+b1) (fp32)
    dim3 g1(MT, F_HID / 128);
    mma_gemm_kernel<<<g1, 512>>>(x, w1thi, w1tlo, h1p, N_NODES, F_HID);
    agg_kernel<F_HID><<<(N_NODES * (F_HID / 8) + 255) / 256, 256>>>(h1p, b1, a1p);

    // layer 2: h2 = a1 @ W2 (fp16 out), out = relu(agg(h2)+b2)
    dim3 g2(MT, F_OUT / 128);
    mma_gemm_kernel<<<g2, 512>>>(a1p, w2thi, w2tlo, h2p, N_NODES, F_OUT);
    agg_kernel<F_OUT><<<(N_NODES * (F_OUT / 8) + 255) / 256, 256>>>(h2p, b2, out);
}

// round 9
// speedup vs baseline: 1.0671x; 1.0671x over previous
#include <cuda_runtime.h>
#include <cuda_bf16.h>
#include <cuda_fp16.h>
#include <cstdint>
#include <math.h>

// ---------------- problem constants ----------------------------------------
#define N_NODES 100000
#define N_EDGES 1600000
#define F_IN    256
#define F_HID   256
#define F_OUT   128
#define K_TOT   256          // K dim for both GEMMs

#define SCAN_CHUNK  1024
#define SCAN_BLOCKS ((N_NODES + SCAN_CHUNK - 1) / SCAN_CHUNK)   // 98

// ---------------- device scratch (static, no allocations) ------------------
__device__ int   g_deg[N_NODES];
__device__ float g_dinv[N_NODES];
__device__ int   g_rowstart[N_NODES + 1];
__device__ int   g_cursor[N_NODES];
__device__ int   g_partial[SCAN_BLOCKS];
__device__ int   g_csr_src[N_EDGES];
__device__ float g_csr_w[N_EDGES];

__device__ __nv_bfloat16 g_w1t_hi[F_HID * K_TOT];     // [256][256] = W1^T
__device__ __nv_bfloat16 g_w1t_lo[F_HID * K_TOT];
__device__ __nv_bfloat16 g_w2t_hi[F_OUT * K_TOT];     // [128][256] = W2^T
__device__ __nv_bfloat16 g_w2t_lo[F_OUT * K_TOT];
__device__ __half g_h1[(size_t)N_NODES * F_HID];       // x @ W1 (fp16)
__device__ float  g_a1[(size_t)N_NODES * F_HID];       // relu(agg(h1)+b1) fp32
__device__ __half g_h2[(size_t)N_NODES * F_OUT];       // a1 @ W2 (fp16)

// ---------------- CSR construction -----------------------------------------

__global__ void init_kernel() {
    int i = blockIdx.x * blockDim.x + threadIdx.x;
    if (i < N_NODES) { g_deg[i] = 1; g_cursor[i] = 0; }
}

__global__ void count_kernel(const int* __restrict__ dst, int E) {
    int e = blockIdx.x * blockDim.x + threadIdx.x;
    if (e < E) atomicAdd(&g_deg[dst[e]], 1);
}

__global__ void dinv_kernel() {
    int i = blockIdx.x * blockDim.x + threadIdx.x;
    if (i < N_NODES) g_dinv[i] = rsqrtf((float)g_deg[i]);
}

__global__ __launch_bounds__(256) void scan_partial_kernel() {
    __shared__ int red[256];
    const int base = blockIdx.x * SCAN_CHUNK;
    int s = 0;
    for (int j = threadIdx.x; j < SCAN_CHUNK; j += 256) {
        int idx = base + j;
        if (idx < N_NODES) s += g_deg[idx] - 1;
    }
    red[threadIdx.x] = s;
    __syncthreads();
    #pragma unroll
    for (int off = 128; off > 0; off >>= 1) {
        if (threadIdx.x < off) red[threadIdx.x] += red[threadIdx.x + off];
        __syncthreads();
    }
    if (threadIdx.x == 0) g_partial[blockIdx.x] = red[0];
}

__global__ void scan_top_kernel() {
    __shared__ int sh[SCAN_BLOCKS];
    for (int i = threadIdx.x; i < SCAN_BLOCKS; i += blockDim.x) sh[i] = g_partial[i];
    __syncthreads();
    if (threadIdx.x == 0) {
        int run = 0;
        for (int i = 0; i < SCAN_BLOCKS; i++) { int v = sh[i]; sh[i] = run; run += v; }
        g_rowstart[N_NODES] = run;
    }
    __syncthreads();
    for (int i = threadIdx.x; i < SCAN_BLOCKS; i += blockDim.x) g_partial[i] = sh[i];
}

__global__ __launch_bounds__(256) void scan_final_kernel() {
    __shared__ int sh[256];
    const int t = threadIdx.x;
    const int idx0 = blockIdx.x * SCAN_CHUNK + t * 4;
    int v[4]; int s = 0;
    #pragma unroll
    for (int j = 0; j < 4; j++) {
        int idx = idx0 + j;
        int d = (idx < N_NODES) ? (g_deg[idx] - 1) : 0;
        v[j] = s; s += d;
    }
    sh[t] = s;
    __syncthreads();
    #pragma unroll
    for (int off = 1; off < 256; off <<= 1) {
        int val = (t >= off) ? sh[t - off] : 0;
        __syncthreads();
        sh[t] += val;
        __syncthreads();
    }
    int excl = ((t == 0) ? 0 : sh[t - 1]) + g_partial[blockIdx.x];
    #pragma unroll
    for (int j = 0; j < 4; j++) {
        int idx = idx0 + j;
        if (idx < N_NODES) g_rowstart[idx] = excl + v[j];
    }
}

__global__ void fill_kernel(const int* __restrict__ src,
                            const int* __restrict__ dst, int E) {
    int e = blockIdx.x * blockDim.x + threadIdx.x;
    if (e < E) {
        int d = dst[e];
        int s = src[e];
        int pos = atomicAdd(&g_cursor[d], 1);
        int idx = g_rowstart[d] + pos;
        g_csr_src[idx] = s;
        g_csr_w[idx]   = g_dinv[s] * g_dinv[d];
    }
}

// ---------------- weight conversion: W [K][N] -> WT hi/lo [N][K] ------------

__global__ void convert_w_kernel(const float* __restrict__ W,
                                 __nv_bfloat16* __restrict__ hi,
                                 __nv_bfloat16* __restrict__ lo,
                                 int K, int N) {
    int i = blockIdx.x * blockDim.x + threadIdx.x;
    if (i >= N * K) return;
    int nrow = i / K;
    int k = i - nrow * K;
    float v = W[(size_t)k * N + nrow];
    __nv_bfloat16 h = __float2bfloat16(v);
    hi[i] = h;
    lo[i] = __float2bfloat16(v - __bfloat162float(h));
}

// ---------------- mma.sync bf16x3 GEMM --------------------------------------
// C[M rows, 64-col slice](fp16) = A[M,256](fp32) @ B^T, B as bf16 (hi,lo).
// A is split to bf16 hi/lo in registers while staging to smem.
// CTA tile 128x64, 8 warps (4 m x 2 n), warp tile 32x32.
// Grid mapping: blockIdx.x = n-slice (fast axis), blockIdx.y = row tile,
// so CTAs sharing an A row-block are launch-adjacent -> A read from DRAM once.

#define LDSK 40   // bf16 elements per smem row (32 data + 8 pad); 80B, 16B-mult

#define MMA_BF16(d, a, b) \
    asm volatile("mma.sync.aligned.m16n8k16.row.col.f32.bf16.bf16.f32 " \
        "{%0,%1,%2,%3}, {%4,%5,%6,%7}, {%8,%9}, {%0,%1,%2,%3};" \
        : "+f"((d)[0]), "+f"((d)[1]), "+f"((d)[2]), "+f"((d)[3]) \
        : "r"((a)[0]), "r"((a)[1]), "r"((a)[2]), "r"((a)[3]), \
          "r"((b)[0]), "r"((b)[1]))

__global__ __launch_bounds__(256)
void mma_gemm_kernel(const float* __restrict__ A,
                     const __nv_bfloat16* __restrict__ Bhi,
                     const __nv_bfloat16* __restrict__ Blo,
                     __half* __restrict__ C, int M, int ldc) {
    __shared__ __align__(16) __nv_bfloat16 sAh[128 * LDSK];
    __shared__ __align__(16) __nv_bfloat16 sAl[128 * LDSK];
    __shared__ __align__(16) __nv_bfloat16 sBh[64 * LDSK];
    __shared__ __align__(16) __nv_bfloat16 sBl[64 * LDSK];

    const int tid  = threadIdx.x;
    const int wid  = tid >> 5;
    const int lane = tid & 31;
    const int warp_m = wid & 3;        // 0..3 -> m offset 32*warp_m
    const int warp_n = wid >> 2;       // 0..1 -> n offset 32*warp_n
    const int block_row = blockIdx.y * 128;    // row tile (slow axis)
    const int n0 = blockIdx.x * 64;            // n slice (fast axis)

    const int g = lane >> 2;           // 0..7
    const int q = lane & 3;            // 0..3

    float acc[8][4];
    #pragma unroll
    for (int i = 0; i < 8; i++)
        #pragma unroll
        for (int j = 0; j < 4; j++) acc[i][j] = 0.0f;

    for (int c = 0; c < 8; c++) {
        const int k0 = c * 32;

        // A chunk: 128 rows x 32 fp32 = 1024 float4; split to hi/lo in regs.
        #pragma unroll
        for (int t = tid; t < 1024; t += 256) {
            const int row = t >> 3;
            const int u   = t & 7;            // float4 index within row
            const int grow = block_row + row;
            float4 v = make_float4(0.f, 0.f, 0.f, 0.f);
            if (grow < M)
                v = *reinterpret_cast<const float4*>(
                    A + (size_t)grow * K_TOT + k0 + u * 4);
            __nv_bfloat16 hx = __float2bfloat16(v.x);
            __nv_bfloat16 hy = __float2bfloat16(v.y);
            __nv_bfloat16 hz = __float2bfloat16(v.z);
            __nv_bfloat16 hw = __float2bfloat16(v.w);
            __nv_bfloat162 h01 = __halves2bfloat162(hx, hy);
            __nv_bfloat162 h23 = __halves2bfloat162(hz, hw);
            __nv_bfloat162 l01 = __halves2bfloat162(
                __float2bfloat16(v.x - __bfloat162float(hx)),
                __float2bfloat16(v.y - __bfloat162float(hy)));
            __nv_bfloat162 l23 = __halves2bfloat162(
                __float2bfloat16(v.z - __bfloat162float(hz)),
                __float2bfloat16(v.w - __bfloat162float(hw)));
            __nv_bfloat162* dh = reinterpret_cast<__nv_bfloat162*>(
                sAh + row * LDSK + u * 4);
            __nv_bfloat162* dl = reinterpret_cast<__nv_bfloat162*>(
                sAl + row * LDSK + u * 4);
            dh[0] = h01; dh[1] = h23;
            dl[0] = l01; dl[1] = l23;
        }
        // B chunk: hi+lo, 64 rows x 4 uint4 each => 512 uint4
        #pragma unroll
        for (int t = tid; t < 512; t += 256) {
            const int arr = t >> 8;
            const int idx = t & 255;
            const int row = idx >> 2;
            const int u   = idx & 3;
            const __nv_bfloat16* src = arr ? Blo : Bhi;
            uint4 v = *reinterpret_cast<const uint4*>(
                src + (size_t)(n0 + row) * K_TOT + k0 + u * 8);
            __nv_bfloat16* dst = (arr ? sBl : sBh) + row * LDSK + u * 8;
            *reinterpret_cast<uint4*>(dst) = v;
        }
        __syncthreads();

        #pragma unroll
        for (int kk = 0; kk < 2; kk++) {
            const int kb = kk * 16;
            uint32_t Ah[2][4], Al[2][4];
            #pragma unroll
            for (int t = 0; t < 2; t++) {
                const int r0 = (warp_m * 32 + t * 16 + g) * LDSK + kb + q * 2;
                const int r1 = r0 + 8 * LDSK;
                Ah[t][0] = *reinterpret_cast<const uint32_t*>(&sAh[r0]);
                Ah[t][1] = *reinterpret_cast<const uint32_t*>(&sAh[r1]);
                Ah[t][2] = *reinterpret_cast<const uint32_t*>(&sAh[r0 + 8]);
                Ah[t][3] = *reinterpret_cast<const uint32_t*>(&sAh[r1 + 8]);
                Al[t][0] = *reinterpret_cast<const uint32_t*>(&sAl[r0]);
                Al[t][1] = *reinterpret_cast<const uint32_t*>(&sAl[r1]);
                Al[t][2] = *reinterpret_cast<const uint32_t*>(&sAl[r0 + 8]);
                Al[t][3] = *reinterpret_cast<const uint32_t*>(&sAl[r1 + 8]);
            }
            uint32_t Bh[4][2], Bl[4][2];
            #pragma unroll
            for (int j = 0; j < 4; j++) {
                const int rb = (warp_n * 32 + j * 8 + g) * LDSK + kb + q * 2;
                Bh[j][0] = *reinterpret_cast<const uint32_t*>(&sBh[rb]);
                Bh[j][1] = *reinterpret_cast<const uint32_t*>(&sBh[rb + 8]);
                Bl[j][0] = *reinterpret_cast<const uint32_t*>(&sBl[rb]);
                Bl[j][1] = *reinterpret_cast<const uint32_t*>(&sBl[rb + 8]);
            }
            #pragma unroll
            for (int t = 0; t < 2; t++)
                #pragma unroll
                for (int j = 0; j < 4; j++) {
                    float* d = acc[t * 4 + j];
                    MMA_BF16(d, Ah[t], Bh[j]);   // hi*hi
                    MMA_BF16(d, Ah[t], Bl[j]);   // hi*lo
                    MMA_BF16(d, Al[t], Bh[j]);   // lo*hi
                }
        }
        __syncthreads();
    }

    // store fp16: c0,c1 -> row g; c2,c3 -> row g+8; cols 2q,2q+1
    #pragma unroll
    for (int t = 0; t < 2; t++) {
        const int row0 = block_row + warp_m * 32 + t * 16 + g;
        #pragma unroll
        for (int j = 0; j < 4; j++) {
            const int col = n0 + warp_n * 32 + j * 8 + q * 2;
            const float* d = acc[t * 4 + j];
            if (row0 < M)
                *reinterpret_cast<__half2*>(C + (size_t)row0 * ldc + col) =
                    __floats2half2_rn(d[0], d[1]);
            if (row0 + 8 < M)
                *reinterpret_cast<__half2*>(C + (size_t)(row0 + 8) * ldc + col) =
                    __floats2half2_rn(d[2], d[3]);
        }
    }
}

// ---------------- sparse aggregation (fp16 gather, fp32 accumulate) --------
// Out[i] = relu( bias + dinv[i]^2 * H[i] + sum_e w_e * H[src_e] )
// F/8 lanes per node; uint4 = 8 halves per lane; 4-edge unroll.
template <int F>
__global__ __launch_bounds__(256)
void agg_kernel(const __half* __restrict__ H, const float* __restrict__ bias,
                float* __restrict__ Out) {
    const int lanes = F / 8;                 // 32 (F=256) or 16 (F=128)
    const int tid = threadIdx.x;
    const int node = blockIdx.x * (256 / lanes) + tid / lanes;
    if (node >= N_NODES) return;
    const int f = (tid % lanes) * 8;

    const float di = g_dinv[node];
    const float w0 = di * di;

    float acc[8];
    {
        uint4 hv = *reinterpret_cast<const uint4*>(H + (size_t)node * F + f);
        const __half2* hp = reinterpret_cast<const __half2*>(&hv);
        #pragma unroll
        for (int j = 0; j < 4; j++) {
            float2 v = __half22float2(hp[j]);
            acc[j * 2 + 0] = fmaf(w0, v.x, bias[f + j * 2 + 0]);
            acc[j * 2 + 1] = fmaf(w0, v.y, bias[f + j * 2 + 1]);
        }
    }
    float acc1[8], acc2[8], acc3[8];
    #pragma unroll
    for (int j = 0; j < 8; j++) { acc1[j] = 0.f; acc2[j] = 0.f; acc3[j] = 0.f; }

    int e = g_rowstart[node];
    const int end = g_rowstart[node + 1];

    for (; e + 4 <= end; e += 4) {
        int   s0 = __ldg(&g_csr_src[e + 0]);
        int   s1 = __ldg(&g_csr_src[e + 1]);
        int   s2 = __ldg(&g_csr_src[e + 2]);
        int   s3 = __ldg(&g_csr_src[e + 3]);
        float w0e = __ldg(&g_csr_w[e + 0]);
        float w1e = __ldg(&g_csr_w[e + 1]);
        float w2e = __ldg(&g_csr_w[e + 2]);
        float w3e = __ldg(&g_csr_w[e + 3]);
        uint4 v0 = *reinterpret_cast<const uint4*>(H + (size_t)s0 * F + f);
        uint4 v1 = *reinterpret_cast<const uint4*>(H + (size_t)s1 * F + f);
        uint4 v2 = *reinterpret_cast<const uint4*>(H + (size_t)s2 * F + f);
        uint4 v3 = *reinterpret_cast<const uint4*>(H + (size_t)s3 * F + f);
        const __half2* p0 = reinterpret_cast<const __half2*>(&v0);
        const __half2* p1 = reinterpret_cast<const __half2*>(&v1);
        const __half2* p2 = reinterpret_cast<const __half2*>(&v2);
        const __half2* p3 = reinterpret_cast<const __half2*>(&v3);
        #pragma unroll
        for (int j = 0; j < 4; j++) {
            float2 f0 = __half22float2(p0[j]);
            float2 f1 = __half22float2(p1[j]);
            float2 f2 = __half22float2(p2[j]);
            float2 f3 = __half22float2(p3[j]);
            acc[j*2+0]  = fmaf(w0e, f0.x, acc[j*2+0]);
            acc[j*2+1]  = fmaf(w0e, f0.y, acc[j*2+1]);
            acc1[j*2+0] = fmaf(w1e, f1.x, acc1[j*2+0]);
            acc1[j*2+1] = fmaf(w1e, f1.y, acc1[j*2+1]);
            acc2[j*2+0] = fmaf(w2e, f2.x, acc2[j*2+0]);
            acc2[j*2+1] = fmaf(w2e, f2.y, acc2[j*2+1]);
            acc3[j*2+0] = fmaf(w3e, f3.x, acc3[j*2+0]);
            acc3[j*2+1] = fmaf(w3e, f3.y, acc3[j*2+1]);
        }
    }
    for (; e < end; e++) {
        int   s = __ldg(&g_csr_src[e]);
        float w = __ldg(&g_csr_w[e]);
        uint4 v = *reinterpret_cast<const uint4*>(H + (size_t)s * F + f);
        const __half2* p = reinterpret_cast<const __half2*>(&v);
        #pragma unroll
        for (int j = 0; j < 4; j++) {
            float2 fv = __half22float2(p[j]);
            acc[j*2+0] = fmaf(w, fv.x, acc[j*2+0]);
            acc[j*2+1] = fmaf(w, fv.y, acc[j*2+1]);
        }
    }

    float4 r0, r1;
    r0.x = fmaxf((acc[0] + acc1[0]) + (acc2[0] + acc3[0]), 0.0f);
    r0.y = fmaxf((acc[1] + acc1[1]) + (acc2[1] + acc3[1]), 0.0f);
    r0.z = fmaxf((acc[2] + acc1[2]) + (acc2[2] + acc3[2]), 0.0f);
    r0.w = fmaxf((acc[3] + acc1[3]) + (acc2[3] + acc3[3]), 0.0f);
    r1.x = fmaxf((acc[4] + acc1[4]) + (acc2[4] + acc3[4]), 0.0f);
    r1.y = fmaxf((acc[5] + acc1[5]) + (acc2[5] + acc3[5]), 0.0f);
    r1.z = fmaxf((acc[6] + acc1[6]) + (acc2[6] + acc3[6]), 0.0f);
    r1.w = fmaxf((acc[7] + acc1[7]) + (acc2[7] + acc3[7]), 0.0f);
    float* dst = Out + (size_t)node * F + f;
    *reinterpret_cast<float4*>(dst)     = r0;
    *reinterpret_cast<float4*>(dst + 4) = r1;
}

// ---------------- launcher ---------------------------------------------------

extern "C" void kernel_launch(void* const* d_in, const int* in_sizes, int n_in,
                              void* d_out, int out_size) {
    const float* x  = (const float*)d_in[0];
    const int*   ei = (const int*)d_in[1];
    const float* W1 = (const float*)d_in[2];
    const float* b1 = (const float*)d_in[3];
    const float* W2 = (const float*)d_in[4];
    const float* b2 = (const float*)d_in[5];
    float* out = (float*)d_out;

    const int E = in_sizes[1] / 2;
    const int* src = ei;
    const int* dst = ei + E;

    __half *h1p = nullptr, *h2p = nullptr;
    float  *a1p = nullptr;
    __nv_bfloat16 *w1thi = nullptr, *w1tlo = nullptr;
    __nv_bfloat16 *w2thi = nullptr, *w2tlo = nullptr;
    cudaGetSymbolAddress((void**)&h1p, g_h1);
    cudaGetSymbolAddress((void**)&h2p, g_h2);
    cudaGetSymbolAddress((void**)&a1p, g_a1);
    cudaGetSymbolAddress((void**)&w1thi, g_w1t_hi);
    cudaGetSymbolAddress((void**)&w1tlo, g_w1t_lo);
    cudaGetSymbolAddress((void**)&w2thi, g_w2t_hi);
    cudaGetSymbolAddress((void**)&w2tlo, g_w2t_lo);

    const int TB = 256;
    // CSR build
    init_kernel<<<(N_NODES + TB - 1) / TB, TB>>>();
    count_kernel<<<(E + TB - 1) / TB, TB>>>(dst, E);
    dinv_kernel<<<(N_NODES + TB - 1) / TB, TB>>>();
    scan_partial_kernel<<<SCAN_BLOCKS, 256>>>();
    scan_top_kernel<<<1, 128>>>();
    scan_final_kernel<<<SCAN_BLOCKS, 256>>>();
    fill_kernel<<<(E + TB - 1) / TB, TB>>>(src, dst, E);

    // weight conversions (tiny)
    convert_w_kernel<<<(F_HID * K_TOT + TB - 1) / TB, TB>>>(W1, w1thi, w1tlo, K_TOT, F_HID);
    convert_w_kernel<<<(F_OUT * K_TOT + TB - 1) / TB, TB>>>(W2, w2thi, w2tlo, K_TOT, F_OUT);

    const int MT = (N_NODES + 127) / 128;   // 782

    // layer 1: h1 = x @ W1 (fp16 out), a1 = relu(agg(h1)+b1) (fp32)
    // grid: x = n-slice (fast), y = row tile -> A row block reused across x
    dim3 g1(F_HID / 64, MT);
    mma_gemm_kernel<<<g1, 256>>>(x, w1thi, w1tlo, h1p, N_NODES, F_HID);
    agg_kernel<F_HID><<<(N_NODES * (F_HID / 8) + 255) / 256, 256>>>(h1p, b1, a1p);

    // layer 2: h2 = a1 @ W2 (fp16 out), out = relu(agg(h2)+b2)
    dim3 g2(F_OUT / 64, MT);
    mma_gemm_kernel<<<g2, 256>>>(a1p, w2thi, w2tlo, h2p, N_NODES, F_OUT);
    agg_kernel<F_OUT><<<(N_NODES * (F_OUT / 8) + 255) / 256, 256>>>(h2p, b2, out);
}

// round 10
// speedup vs baseline: 1.1369x; 1.0654x over previous
#include <cuda_runtime.h>
#include <cuda_bf16.h>
#include <cuda_fp16.h>
#include <cstdint>
#include <math.h>

// ---------------- problem constants ----------------------------------------
#define N_NODES 100000
#define N_EDGES 1600000
#define F_IN    256
#define F_HID   256
#define F_OUT   128
#define K_TOT   256          // K dim for both GEMMs

#define SCAN_CHUNK  1024
#define SCAN_BLOCKS ((N_NODES + SCAN_CHUNK - 1) / SCAN_CHUNK)   // 98

// ---------------- device scratch (static, no allocations) ------------------
__device__ int   g_deg[N_NODES];
__device__ float g_dinv[N_NODES];
__device__ int   g_rowstart[N_NODES + 1];
__device__ int   g_cursor[N_NODES];
__device__ int   g_partial[SCAN_BLOCKS];
__device__ int   g_csr_src[N_EDGES];
__device__ float g_csr_w[N_EDGES];

__device__ __nv_bfloat16 g_w1t_hi[F_HID * K_TOT];     // [256][256] = W1^T
__device__ __nv_bfloat16 g_w1t_lo[F_HID * K_TOT];
__device__ __nv_bfloat16 g_w2t_hi[F_OUT * K_TOT];     // [128][256] = W2^T
__device__ __nv_bfloat16 g_w2t_lo[F_OUT * K_TOT];
__device__ __half g_h1[(size_t)N_NODES * F_HID];       // x @ W1 (fp16)
__device__ float  g_a1[(size_t)N_NODES * F_HID];       // relu(agg(h1)+b1) fp32
__device__ __half g_h2[(size_t)N_NODES * F_OUT];       // a1 @ W2 (fp16)

// ---------------- CSR construction -----------------------------------------

__global__ void init_kernel() {
    int i = blockIdx.x * blockDim.x + threadIdx.x;
    if (i < N_NODES) { g_deg[i] = 1; g_cursor[i] = 0; }
}

__global__ void count_kernel(const int* __restrict__ dst, int E) {
    int e = blockIdx.x * blockDim.x + threadIdx.x;
    if (e < E) atomicAdd(&g_deg[dst[e]], 1);
}

__global__ void dinv_kernel() {
    int i = blockIdx.x * blockDim.x + threadIdx.x;
    if (i < N_NODES) g_dinv[i] = rsqrtf((float)g_deg[i]);
}

__global__ __launch_bounds__(256) void scan_partial_kernel() {
    __shared__ int red[256];
    const int base = blockIdx.x * SCAN_CHUNK;
    int s = 0;
    for (int j = threadIdx.x; j < SCAN_CHUNK; j += 256) {
        int idx = base + j;
        if (idx < N_NODES) s += g_deg[idx] - 1;
    }
    red[threadIdx.x] = s;
    __syncthreads();
    #pragma unroll
    for (int off = 128; off > 0; off >>= 1) {
        if (threadIdx.x < off) red[threadIdx.x] += red[threadIdx.x + off];
        __syncthreads();
    }
    if (threadIdx.x == 0) g_partial[blockIdx.x] = red[0];
}

__global__ void scan_top_kernel() {
    __shared__ int sh[SCAN_BLOCKS];
    for (int i = threadIdx.x; i < SCAN_BLOCKS; i += blockDim.x) sh[i] = g_partial[i];
    __syncthreads();
    if (threadIdx.x == 0) {
        int run = 0;
        for (int i = 0; i < SCAN_BLOCKS; i++) { int v = sh[i]; sh[i] = run; run += v; }
        g_rowstart[N_NODES] = run;
    }
    __syncthreads();
    for (int i = threadIdx.x; i < SCAN_BLOCKS; i += blockDim.x) g_partial[i] = sh[i];
}

__global__ __launch_bounds__(256) void scan_final_kernel() {
    __shared__ int sh[256];
    const int t = threadIdx.x;
    const int idx0 = blockIdx.x * SCAN_CHUNK + t * 4;
    int v[4]; int s = 0;
    #pragma unroll
    for (int j = 0; j < 4; j++) {
        int idx = idx0 + j;
        int d = (idx < N_NODES) ? (g_deg[idx] - 1) : 0;
        v[j] = s; s += d;
    }
    sh[t] = s;
    __syncthreads();
    #pragma unroll
    for (int off = 1; off < 256; off <<= 1) {
        int val = (t >= off) ? sh[t - off] : 0;
        __syncthreads();
        sh[t] += val;
        __syncthreads();
    }
    int excl = ((t == 0) ? 0 : sh[t - 1]) + g_partial[blockIdx.x];
    #pragma unroll
    for (int j = 0; j < 4; j++) {
        int idx = idx0 + j;
        if (idx < N_NODES) g_rowstart[idx] = excl + v[j];
    }
}

__global__ void fill_kernel(const int* __restrict__ src,
                            const int* __restrict__ dst, int E) {
    int e = blockIdx.x * blockDim.x + threadIdx.x;
    if (e < E) {
        int d = dst[e];
        int s = src[e];
        int pos = atomicAdd(&g_cursor[d], 1);
        int idx = g_rowstart[d] + pos;
        g_csr_src[idx] = s;
        g_csr_w[idx]   = g_dinv[s] * g_dinv[d];
    }
}

// ---------------- weight conversion: W [K][N] -> WT hi/lo [N][K] ------------

__global__ void convert_w_kernel(const float* __restrict__ W,
                                 __nv_bfloat16* __restrict__ hi,
                                 __nv_bfloat16* __restrict__ lo,
                                 int K, int N) {
    int i = blockIdx.x * blockDim.x + threadIdx.x;
    if (i >= N * K) return;
    int nrow = i / K;
    int k = i - nrow * K;
    float v = W[(size_t)k * N + nrow];
    __nv_bfloat16 h = __float2bfloat16(v);
    hi[i] = h;
    lo[i] = __float2bfloat16(v - __bfloat162float(h));
}

// ---------------- mma.sync bf16x3 GEMM --------------------------------------
// C[M rows, 64-col slice](fp16) = A[M,256](fp32) @ B^T, B as bf16 (hi,lo).
// A is split to bf16 hi/lo in registers while staging to smem.
// CTA tile 128x64, 8 warps (4 m x 2 n), warp tile 32x32.

#define LDSK 40   // bf16 elements per smem row (32 data + 8 pad); 80B, 16B-mult

#define MMA_BF16(d, a, b) \
    asm volatile("mma.sync.aligned.m16n8k16.row.col.f32.bf16.bf16.f32 " \
        "{%0,%1,%2,%3}, {%4,%5,%6,%7}, {%8,%9}, {%0,%1,%2,%3};" \
        : "+f"((d)[0]), "+f"((d)[1]), "+f"((d)[2]), "+f"((d)[3]) \
        : "r"((a)[0]), "r"((a)[1]), "r"((a)[2]), "r"((a)[3]), \
          "r"((b)[0]), "r"((b)[1]))

__global__ __launch_bounds__(256)
void mma_gemm_kernel(const float* __restrict__ A,
                     const __nv_bfloat16* __restrict__ Bhi,
                     const __nv_bfloat16* __restrict__ Blo,
                     __half* __restrict__ C, int M, int ldc) {
    __shared__ __align__(16) __nv_bfloat16 sAh[128 * LDSK];
    __shared__ __align__(16) __nv_bfloat16 sAl[128 * LDSK];
    __shared__ __align__(16) __nv_bfloat16 sBh[64 * LDSK];
    __shared__ __align__(16) __nv_bfloat16 sBl[64 * LDSK];

    const int tid  = threadIdx.x;
    const int wid  = tid >> 5;
    const int lane = tid & 31;
    const int warp_m = wid & 3;        // 0..3 -> m offset 32*warp_m
    const int warp_n = wid >> 2;       // 0..1 -> n offset 32*warp_n
    const int block_row = blockIdx.x * 128;
    const int n0 = blockIdx.y * 64;

    const int g = lane >> 2;           // 0..7
    const int q = lane & 3;            // 0..3

    float acc[8][4];
    #pragma unroll
    for (int i = 0; i < 8; i++)
        #pragma unroll
        for (int j = 0; j < 4; j++) acc[i][j] = 0.0f;

    for (int c = 0; c < 8; c++) {
        const int k0 = c * 32;

        // A chunk: 128 rows x 32 fp32 = 1024 float4; split to hi/lo in regs.
        #pragma unroll
        for (int t = tid; t < 1024; t += 256) {
            const int row = t >> 3;
            const int u   = t & 7;            // float4 index within row
            const int grow = block_row + row;
            float4 v = make_float4(0.f, 0.f, 0.f, 0.f);
            if (grow < M)
                v = *reinterpret_cast<const float4*>(
                    A + (size_t)grow * K_TOT + k0 + u * 4);
            __nv_bfloat16 hx = __float2bfloat16(v.x);
            __nv_bfloat16 hy = __float2bfloat16(v.y);
            __nv_bfloat16 hz = __float2bfloat16(v.z);
            __nv_bfloat16 hw = __float2bfloat16(v.w);
            __nv_bfloat162 h01 = __halves2bfloat162(hx, hy);
            __nv_bfloat162 h23 = __halves2bfloat162(hz, hw);
            __nv_bfloat162 l01 = __halves2bfloat162(
                __float2bfloat16(v.x - __bfloat162float(hx)),
                __float2bfloat16(v.y - __bfloat162float(hy)));
            __nv_bfloat162 l23 = __halves2bfloat162(
                __float2bfloat16(v.z - __bfloat162float(hz)),
                __float2bfloat16(v.w - __bfloat162float(hw)));
            __nv_bfloat162* dh = reinterpret_cast<__nv_bfloat162*>(
                sAh + row * LDSK + u * 4);
            __nv_bfloat162* dl = reinterpret_cast<__nv_bfloat162*>(
                sAl + row * LDSK + u * 4);
            dh[0] = h01; dh[1] = h23;
            dl[0] = l01; dl[1] = l23;
        }
        // B chunk: hi+lo, 64 rows x 4 uint4 each => 512 uint4
        #pragma unroll
        for (int t = tid; t < 512; t += 256) {
            const int arr = t >> 8;
            const int idx = t & 255;
            const int row = idx >> 2;
            const int u   = idx & 3;
            const __nv_bfloat16* src = arr ? Blo : Bhi;
            uint4 v = *reinterpret_cast<const uint4*>(
                src + (size_t)(n0 + row) * K_TOT + k0 + u * 8);
            __nv_bfloat16* dst = (arr ? sBl : sBh) + row * LDSK + u * 8;
            *reinterpret_cast<uint4*>(dst) = v;
        }
        __syncthreads();

        #pragma unroll
        for (int kk = 0; kk < 2; kk++) {
            const int kb = kk * 16;
            uint32_t Ah[2][4], Al[2][4];
            #pragma unroll
            for (int t = 0; t < 2; t++) {
                const int r0 = (warp_m * 32 + t * 16 + g) * LDSK + kb + q * 2;
                const int r1 = r0 + 8 * LDSK;
                Ah[t][0] = *reinterpret_cast<const uint32_t*>(&sAh[r0]);
                Ah[t][1] = *reinterpret_cast<const uint32_t*>(&sAh[r1]);
                Ah[t][2] = *reinterpret_cast<const uint32_t*>(&sAh[r0 + 8]);
                Ah[t][3] = *reinterpret_cast<const uint32_t*>(&sAh[r1 + 8]);
                Al[t][0] = *reinterpret_cast<const uint32_t*>(&sAl[r0]);
                Al[t][1] = *reinterpret_cast<const uint32_t*>(&sAl[r1]);
                Al[t][2] = *reinterpret_cast<const uint32_t*>(&sAl[r0 + 8]);
                Al[t][3] = *reinterpret_cast<const uint32_t*>(&sAl[r1 + 8]);
            }
            uint32_t Bh[4][2], Bl[4][2];
            #pragma unroll
            for (int j = 0; j < 4; j++) {
                const int rb = (warp_n * 32 + j * 8 + g) * LDSK + kb + q * 2;
                Bh[j][0] = *reinterpret_cast<const uint32_t*>(&sBh[rb]);
                Bh[j][1] = *reinterpret_cast<const uint32_t*>(&sBh[rb + 8]);
                Bl[j][0] = *reinterpret_cast<const uint32_t*>(&sBl[rb]);
                Bl[j][1] = *reinterpret_cast<const uint32_t*>(&sBl[rb + 8]);
            }
            #pragma unroll
            for (int t = 0; t < 2; t++)
                #pragma unroll
                for (int j = 0; j < 4; j++) {
                    float* d = acc[t * 4 + j];
                    MMA_BF16(d, Ah[t], Bh[j]);   // hi*hi
                    MMA_BF16(d, Ah[t], Bl[j]);   // hi*lo
                    MMA_BF16(d, Al[t], Bh[j]);   // lo*hi
                }
        }
        __syncthreads();
    }

    // store fp16: c0,c1 -> row g; c2,c3 -> row g+8; cols 2q,2q+1
    #pragma unroll
    for (int t = 0; t < 2; t++) {
        const int row0 = block_row + warp_m * 32 + t * 16 + g;
        #pragma unroll
        for (int j = 0; j < 4; j++) {
            const int col = n0 + warp_n * 32 + j * 8 + q * 2;
            const float* d = acc[t * 4 + j];
            if (row0 < M)
                *reinterpret_cast<__half2*>(C + (size_t)row0 * ldc + col) =
                    __floats2half2_rn(d[0], d[1]);
            if (row0 + 8 < M)
                *reinterpret_cast<__half2*>(C + (size_t)(row0 + 8) * ldc + col) =
                    __floats2half2_rn(d[2], d[3]);
        }
    }
}

// ---------------- sparse aggregation (fp16 gather, fp32 accumulate) --------
// Out[i] = relu( bias + dinv[i]^2 * H[i] + sum_e w_e * H[src_e] )
// F/8 lanes per node; uint4 = 8 halves per lane; 4-edge unroll.
template <int F>
__global__ __launch_bounds__(256)
void agg_kernel(const __half* __restrict__ H, const float* __restrict__ bias,
                float* __restrict__ Out) {
    const int lanes = F / 8;                 // 32 (F=256) or 16 (F=128)
    const int tid = threadIdx.x;
    const int node = blockIdx.x * (256 / lanes) + tid / lanes;
    if (node >= N_NODES) return;
    const int f = (tid % lanes) * 8;

    const float di = g_dinv[node];
    const float w0 = di * di;

    float acc[8];
    {
        uint4 hv = *reinterpret_cast<const uint4*>(H + (size_t)node * F + f);
        const __half2* hp = reinterpret_cast<const __half2*>(&hv);
        #pragma unroll
        for (int j = 0; j < 4; j++) {
            float2 v = __half22float2(hp[j]);
            acc[j * 2 + 0] = fmaf(w0, v.x, bias[f + j * 2 + 0]);
            acc[j * 2 + 1] = fmaf(w0, v.y, bias[f + j * 2 + 1]);
        }
    }
    float acc1[8], acc2[8], acc3[8];
    #pragma unroll
    for (int j = 0; j < 8; j++) { acc1[j] = 0.f; acc2[j] = 0.f; acc3[j] = 0.f; }

    int e = g_rowstart[node];
    const int end = g_rowstart[node + 1];

    for (; e + 4 <= end; e += 4) {
        int   s0 = __ldg(&g_csr_src[e + 0]);
        int   s1 = __ldg(&g_csr_src[e + 1]);
        int   s2 = __ldg(&g_csr_src[e + 2]);
        int   s3 = __ldg(&g_csr_src[e + 3]);
        float w0e = __ldg(&g_csr_w[e + 0]);
        float w1e = __ldg(&g_csr_w[e + 1]);
        float w2e = __ldg(&g_csr_w[e + 2]);
        float w3e = __ldg(&g_csr_w[e + 3]);
        uint4 v0 = *reinterpret_cast<const uint4*>(H + (size_t)s0 * F + f);
        uint4 v1 = *reinterpret_cast<const uint4*>(H + (size_t)s1 * F + f);
        uint4 v2 = *reinterpret_cast<const uint4*>(H + (size_t)s2 * F + f);
        uint4 v3 = *reinterpret_cast<const uint4*>(H + (size_t)s3 * F + f);
        const __half2* p0 = reinterpret_cast<const __half2*>(&v0);
        const __half2* p1 = reinterpret_cast<const __half2*>(&v1);
        const __half2* p2 = reinterpret_cast<const __half2*>(&v2);
        const __half2* p3 = reinterpret_cast<const __half2*>(&v3);
        #pragma unroll
        for (int j = 0; j < 4; j++) {
            float2 f0 = __half22float2(p0[j]);
            float2 f1 = __half22float2(p1[j]);
            float2 f2 = __half22float2(p2[j]);
            float2 f3 = __half22float2(p3[j]);
            acc[j*2+0]  = fmaf(w0e, f0.x, acc[j*2+0]);
            acc[j*2+1]  = fmaf(w0e, f0.y, acc[j*2+1]);
            acc1[j*2+0] = fmaf(w1e, f1.x, acc1[j*2+0]);
            acc1[j*2+1] = fmaf(w1e, f1.y, acc1[j*2+1]);
            acc2[j*2+0] = fmaf(w2e, f2.x, acc2[j*2+0]);
            acc2[j*2+1] = fmaf(w2e, f2.y, acc2[j*2+1]);
            acc3[j*2+0] = fmaf(w3e, f3.x, acc3[j*2+0]);
            acc3[j*2+1] = fmaf(w3e, f3.y, acc3[j*2+1]);
        }
    }
    for (; e < end; e++) {
        int   s = __ldg(&g_csr_src[e]);
        float w = __ldg(&g_csr_w[e]);
        uint4 v = *reinterpret_cast<const uint4*>(H + (size_t)s * F + f);
        const __half2* p = reinterpret_cast<const __half2*>(&v);
        #pragma unroll
        for (int j = 0; j < 4; j++) {
            float2 fv = __half22float2(p[j]);
            acc[j*2+0] = fmaf(w, fv.x, acc[j*2+0]);
            acc[j*2+1] = fmaf(w, fv.y, acc[j*2+1]);
        }
    }

    float4 r0, r1;
    r0.x = fmaxf((acc[0] + acc1[0]) + (acc2[0] + acc3[0]), 0.0f);
    r0.y = fmaxf((acc[1] + acc1[1]) + (acc2[1] + acc3[1]), 0.0f);
    r0.z = fmaxf((acc[2] + acc1[2]) + (acc2[2] + acc3[2]), 0.0f);
    r0.w = fmaxf((acc[3] + acc1[3]) + (acc2[3] + acc3[3]), 0.0f);
    r1.x = fmaxf((acc[4] + acc1[4]) + (acc2[4] + acc3[4]), 0.0f);
    r1.y = fmaxf((acc[5] + acc1[5]) + (acc2[5] + acc3[5]), 0.0f);
    r1.z = fmaxf((acc[6] + acc1[6]) + (acc2[6] + acc3[6]), 0.0f);
    r1.w = fmaxf((acc[7] + acc1[7]) + (acc2[7] + acc3[7]), 0.0f);
    float* dst = Out + (size_t)node * F + f;
    *reinterpret_cast<float4*>(dst)     = r0;
    *reinterpret_cast<float4*>(dst + 4) = r1;
}

// ---------------- launcher ---------------------------------------------------

extern "C" void kernel_launch(void* const* d_in, const int* in_sizes, int n_in,
                              void* d_out, int out_size) {
    const float* x  = (const float*)d_in[0];
    const int*   ei = (const int*)d_in[1];
    const float* W1 = (const float*)d_in[2];
    const float* b1 = (const float*)d_in[3];
    const float* W2 = (const float*)d_in[4];
    const float* b2 = (const float*)d_in[5];
    float* out = (float*)d_out;

    const int E = in_sizes[1] / 2;
    const int* src = ei;
    const int* dst = ei + E;

    __half *h1p = nullptr, *h2p = nullptr;
    float  *a1p = nullptr;
    __nv_bfloat16 *w1thi = nullptr, *w1tlo = nullptr;
    __nv_bfloat16 *w2thi = nullptr, *w2tlo = nullptr;
    cudaGetSymbolAddress((void**)&h1p, g_h1);
    cudaGetSymbolAddress((void**)&h2p, g_h2);
    cudaGetSymbolAddress((void**)&a1p, g_a1);
    cudaGetSymbolAddress((void**)&w1thi, g_w1t_hi);
    cudaGetSymbolAddress((void**)&w1tlo, g_w1t_lo);
    cudaGetSymbolAddress((void**)&w2thi, g_w2t_hi);
    cudaGetSymbolAddress((void**)&w2tlo, g_w2t_lo);

    // lazily-created side stream + events (host-side objects; created once,
    // reused every call -> identical captured graph each time)
    static cudaStream_t sB = nullptr;
    static cudaEvent_t evFork = nullptr, evJoin = nullptr;
    if (sB == nullptr) {
        cudaStreamCreateWithFlags(&sB, cudaStreamNonBlocking);
        cudaEventCreateWithFlags(&evFork, cudaEventDisableTiming);
        cudaEventCreateWithFlags(&evJoin, cudaEventDisableTiming);
    }

    const int TB = 256;
    const int MT = (N_NODES + 127) / 128;   // 782

    // ---- fork: side stream B inherits current state of the main stream ----
    cudaEventRecord(evFork, 0);
    cudaStreamWaitEvent(sB, evFork, 0);

    // stream B: CSR build chain + W2 conversion (independent of GEMM1)
    init_kernel<<<(N_NODES + TB - 1) / TB, TB, 0, sB>>>();
    count_kernel<<<(E + TB - 1) / TB, TB, 0, sB>>>(dst, E);
    dinv_kernel<<<(N_NODES + TB - 1) / TB, TB, 0, sB>>>();
    scan_partial_kernel<<<SCAN_BLOCKS, 256, 0, sB>>>();
    scan_top_kernel<<<1, 128, 0, sB>>>();
    scan_final_kernel<<<SCAN_BLOCKS, 256, 0, sB>>>();
    fill_kernel<<<(E + TB - 1) / TB, TB, 0, sB>>>(src, dst, E);
    convert_w_kernel<<<(F_OUT * K_TOT + TB - 1) / TB, TB, 0, sB>>>(
        W2, w2thi, w2tlo, K_TOT, F_OUT);
    cudaEventRecord(evJoin, sB);

    // main stream: W1 conversion + GEMM1 (needs only x, W1)
    convert_w_kernel<<<(F_HID * K_TOT + TB - 1) / TB, TB>>>(
        W1, w1thi, w1tlo, K_TOT, F_HID);
    dim3 g1(MT, F_HID / 64);
    mma_gemm_kernel<<<g1, 256>>>(x, w1thi, w1tlo, h1p, N_NODES, F_HID);

    // ---- join: main stream waits for CSR chain before aggregation ----
    cudaStreamWaitEvent(0, evJoin, 0);

    // layer 1 aggregation, layer 2 GEMM + aggregation (serial dependencies)
    agg_kernel<F_HID><<<(N_NODES * (F_HID / 8) + 255) / 256, 256>>>(h1p, b1, a1p);
    dim3 g2(MT, F_OUT / 64);
    mma_gemm_kernel<<<g2, 256>>>(a1p, w2thi, w2tlo, h2p, N_NODES, F_OUT);
    agg_kernel<F_OUT><<<(N_NODES * (F_OUT / 8) + 255) / 256, 256>>>(h2p, b2, out);
}

// round 11
// speedup vs baseline: 1.1658x; 1.0254x over previous
#include <cuda_runtime.h>
#include <cuda_bf16.h>
#include <cuda_fp16.h>
#include <cstdint>
#include <math.h>

// ---------------- problem constants ----------------------------------------
#define N_NODES 100000
#define N_EDGES 1600000
#define F_IN    256
#define F_HID   256
#define F_OUT   128
#define K_TOT   256          // K dim for both GEMMs

#define SCAN_CHUNK  1024
#define SCAN_BLOCKS ((N_NODES + SCAN_CHUNK - 1) / SCAN_CHUNK)   // 98

// ---------------- device scratch (static, no allocations) ------------------
__device__ int   g_deg[N_NODES];
__device__ float g_dinv[N_NODES];
__device__ int   g_rowstart[N_NODES + 1];
__device__ int   g_cursor[N_NODES];
__device__ int   g_partial[SCAN_BLOCKS];
__device__ int   g_csr_src[N_EDGES];
__device__ float g_csr_w[N_EDGES];

__device__ __nv_bfloat16 g_w1t_hi[F_HID * K_TOT];     // [256][256] = W1^T
__device__ __nv_bfloat16 g_w1t_lo[F_HID * K_TOT];
__device__ __nv_bfloat16 g_w2t_hi[F_OUT * K_TOT];     // [128][256] = W2^T
__device__ __nv_bfloat16 g_w2t_lo[F_OUT * K_TOT];
__device__ __half g_h1[(size_t)N_NODES * F_HID];       // x @ W1 (fp16)
__device__ __half g_a1[(size_t)N_NODES * F_HID];       // relu(agg(h1)+b1) fp16
__device__ __half g_h2[(size_t)N_NODES * F_OUT];       // a1 @ W2 (fp16)

// ---------------- CSR construction -----------------------------------------

__global__ void init_kernel() {
    int i = blockIdx.x * blockDim.x + threadIdx.x;
    if (i < N_NODES) { g_deg[i] = 1; g_cursor[i] = 0; }
}

__global__ void count_kernel(const int* __restrict__ dst, int E) {
    int e = blockIdx.x * blockDim.x + threadIdx.x;
    if (e < E) atomicAdd(&g_deg[dst[e]], 1);
}

__global__ void dinv_kernel() {
    int i = blockIdx.x * blockDim.x + threadIdx.x;
    if (i < N_NODES) g_dinv[i] = rsqrtf((float)g_deg[i]);
}

__global__ __launch_bounds__(256) void scan_partial_kernel() {
    __shared__ int red[256];
    const int base = blockIdx.x * SCAN_CHUNK;
    int s = 0;
    for (int j = threadIdx.x; j < SCAN_CHUNK; j += 256) {
        int idx = base + j;
        if (idx < N_NODES) s += g_deg[idx] - 1;
    }
    red[threadIdx.x] = s;
    __syncthreads();
    #pragma unroll
    for (int off = 128; off > 0; off >>= 1) {
        if (threadIdx.x < off) red[threadIdx.x] += red[threadIdx.x + off];
        __syncthreads();
    }
    if (threadIdx.x == 0) g_partial[blockIdx.x] = red[0];
}

__global__ void scan_top_kernel() {
    __shared__ int sh[SCAN_BLOCKS];
    for (int i = threadIdx.x; i < SCAN_BLOCKS; i += blockDim.x) sh[i] = g_partial[i];
    __syncthreads();
    if (threadIdx.x == 0) {
        int run = 0;
        for (int i = 0; i < SCAN_BLOCKS; i++) { int v = sh[i]; sh[i] = run; run += v; }
        g_rowstart[N_NODES] = run;
    }
    __syncthreads();
    for (int i = threadIdx.x; i < SCAN_BLOCKS; i += blockDim.x) g_partial[i] = sh[i];
}

__global__ __launch_bounds__(256) void scan_final_kernel() {
    __shared__ int sh[256];
    const int t = threadIdx.x;
    const int idx0 = blockIdx.x * SCAN_CHUNK + t * 4;
    int v[4]; int s = 0;
    #pragma unroll
    for (int j = 0; j < 4; j++) {
        int idx = idx0 + j;
        int d = (idx < N_NODES) ? (g_deg[idx] - 1) : 0;
        v[j] = s; s += d;
    }
    sh[t] = s;
    __syncthreads();
    #pragma unroll
    for (int off = 1; off < 256; off <<= 1) {
        int val = (t >= off) ? sh[t - off] : 0;
        __syncthreads();
        sh[t] += val;
        __syncthreads();
    }
    int excl = ((t == 0) ? 0 : sh[t - 1]) + g_partial[blockIdx.x];
    #pragma unroll
    for (int j = 0; j < 4; j++) {
        int idx = idx0 + j;
        if (idx < N_NODES) g_rowstart[idx] = excl + v[j];
    }
}

__global__ void fill_kernel(const int* __restrict__ src,
                            const int* __restrict__ dst, int E) {
    int e = blockIdx.x * blockDim.x + threadIdx.x;
    if (e < E) {
        int d = dst[e];
        int s = src[e];
        int pos = atomicAdd(&g_cursor[d], 1);
        int idx = g_rowstart[d] + pos;
        g_csr_src[idx] = s;
        g_csr_w[idx]   = g_dinv[s] * g_dinv[d];
    }
}

// ---------------- weight conversion: W [K][N] -> WT hi/lo [N][K] ------------

__global__ void convert_w_kernel(const float* __restrict__ W,
                                 __nv_bfloat16* __restrict__ hi,
                                 __nv_bfloat16* __restrict__ lo,
                                 int K, int N) {
    int i = blockIdx.x * blockDim.x + threadIdx.x;
    if (i >= N * K) return;
    int nrow = i / K;
    int k = i - nrow * K;
    float v = W[(size_t)k * N + nrow];
    __nv_bfloat16 h = __float2bfloat16(v);
    hi[i] = h;
    lo[i] = __float2bfloat16(v - __bfloat162float(h));
}

// ---------------- mma.sync bf16x3 GEMM --------------------------------------
// C[M rows, 64-col slice](fp16) = A[M,256] @ B^T, B as bf16 (hi,lo).
// A (fp32 or fp16) is split to bf16 hi/lo in registers while staging to smem.
// CTA tile 128x64, 8 warps (4 m x 2 n), warp tile 32x32.

#define LDSK 40   // bf16 elements per smem row (32 data + 8 pad); 80B, 16B-mult

#define MMA_BF16(d, a, b) \
    asm volatile("mma.sync.aligned.m16n8k16.row.col.f32.bf16.bf16.f32 " \
        "{%0,%1,%2,%3}, {%4,%5,%6,%7}, {%8,%9}, {%0,%1,%2,%3};" \
        : "+f"((d)[0]), "+f"((d)[1]), "+f"((d)[2]), "+f"((d)[3]) \
        : "r"((a)[0]), "r"((a)[1]), "r"((a)[2]), "r"((a)[3]), \
          "r"((b)[0]), "r"((b)[1]))

template <typename TA>
__global__ __launch_bounds__(256)
void mma_gemm_kernel(const TA* __restrict__ A,
                     const __nv_bfloat16* __restrict__ Bhi,
                     const __nv_bfloat16* __restrict__ Blo,
                     __half* __restrict__ C, int M, int ldc) {
    __shared__ __align__(16) __nv_bfloat16 sAh[128 * LDSK];
    __shared__ __align__(16) __nv_bfloat16 sAl[128 * LDSK];
    __shared__ __align__(16) __nv_bfloat16 sBh[64 * LDSK];
    __shared__ __align__(16) __nv_bfloat16 sBl[64 * LDSK];

    const int tid  = threadIdx.x;
    const int wid  = tid >> 5;
    const int lane = tid & 31;
    const int warp_m = wid & 3;        // 0..3 -> m offset 32*warp_m
    const int warp_n = wid >> 2;       // 0..1 -> n offset 32*warp_n
    const int block_row = blockIdx.x * 128;
    const int n0 = blockIdx.y * 64;

    const int g = lane >> 2;           // 0..7
    const int q = lane & 3;            // 0..3

    float acc[8][4];
    #pragma unroll
    for (int i = 0; i < 8; i++)
        #pragma unroll
        for (int j = 0; j < 4; j++) acc[i][j] = 0.0f;

    for (int c = 0; c < 8; c++) {
        const int k0 = c * 32;

        if constexpr (sizeof(TA) == 4) {
            // fp32 A: 128 rows x 8 float4 = 1024; split to hi/lo in regs.
            #pragma unroll
            for (int t = tid; t < 1024; t += 256) {
                const int row = t >> 3;
                const int u   = t & 7;        // float4 index within row
                const int grow = block_row + row;
                float4 v = make_float4(0.f, 0.f, 0.f, 0.f);
                if (grow < M)
                    v = *reinterpret_cast<const float4*>(
                        (const float*)A + (size_t)grow * K_TOT + k0 + u * 4);
                __nv_bfloat16 hx = __float2bfloat16(v.x);
                __nv_bfloat16 hy = __float2bfloat16(v.y);
                __nv_bfloat16 hz = __float2bfloat16(v.z);
                __nv_bfloat16 hw = __float2bfloat16(v.w);
                __nv_bfloat162* dh = reinterpret_cast<__nv_bfloat162*>(
                    sAh + row * LDSK + u * 4);
                __nv_bfloat162* dl = reinterpret_cast<__nv_bfloat162*>(
                    sAl + row * LDSK + u * 4);
                dh[0] = __halves2bfloat162(hx, hy);
                dh[1] = __halves2bfloat162(hz, hw);
                dl[0] = __halves2bfloat162(
                    __float2bfloat16(v.x - __bfloat162float(hx)),
                    __float2bfloat16(v.y - __bfloat162float(hy)));
                dl[1] = __halves2bfloat162(
                    __float2bfloat16(v.z - __bfloat162float(hz)),
                    __float2bfloat16(v.w - __bfloat162float(hw)));
            }
        } else {
            // fp16 A: 128 rows x 4 uint4 (8 halves each) = 512; exact split.
            #pragma unroll
            for (int t = tid; t < 512; t += 256) {
                const int row = t >> 2;
                const int u   = t & 3;        // uint4 index within row
                const int grow = block_row + row;
                uint4 hv = make_uint4(0u, 0u, 0u, 0u);
                if (grow < M)
                    hv = *reinterpret_cast<const uint4*>(
                        (const __half*)A + (size_t)grow * K_TOT + k0 + u * 8);
                const __half2* hp = reinterpret_cast<const __half2*>(&hv);
                __nv_bfloat162 dh[4], dl[4];
                #pragma unroll
                for (int j = 0; j < 4; j++) {
                    float2 fv = __half22float2(hp[j]);
                    __nv_bfloat16 hx = __float2bfloat16(fv.x);
                    __nv_bfloat16 hy = __float2bfloat16(fv.y);
                    dh[j] = __halves2bfloat162(hx, hy);
                    dl[j] = __halves2bfloat162(
                        __float2bfloat16(fv.x - __bfloat162float(hx)),
                        __float2bfloat16(fv.y - __bfloat162float(hy)));
                }
                *reinterpret_cast<uint4*>(sAh + row * LDSK + u * 8) =
                    *reinterpret_cast<const uint4*>(dh);
                *reinterpret_cast<uint4*>(sAl + row * LDSK + u * 8) =
                    *reinterpret_cast<const uint4*>(dl);
            }
        }
        // B chunk: hi+lo, 64 rows x 4 uint4 each => 512 uint4
        #pragma unroll
        for (int t = tid; t < 512; t += 256) {
            const int arr = t >> 8;
            const int idx = t & 255;
            const int row = idx >> 2;
            const int u   = idx & 3;
            const __nv_bfloat16* srcB = arr ? Blo : Bhi;
            uint4 v = *reinterpret_cast<const uint4*>(
                srcB + (size_t)(n0 + row) * K_TOT + k0 + u * 8);
            __nv_bfloat16* dstB = (arr ? sBl : sBh) + row * LDSK + u * 8;
            *reinterpret_cast<uint4*>(dstB) = v;
        }
        __syncthreads();

        #pragma unroll
        for (int kk = 0; kk < 2; kk++) {
            const int kb = kk * 16;
            uint32_t Ah[2][4], Al[2][4];
            #pragma unroll
            for (int t = 0; t < 2; t++) {
                const int r0 = (warp_m * 32 + t * 16 + g) * LDSK + kb + q * 2;
                const int r1 = r0 + 8 * LDSK;
                Ah[t][0] = *reinterpret_cast<const uint32_t*>(&sAh[r0]);
                Ah[t][1] = *reinterpret_cast<const uint32_t*>(&sAh[r1]);
                Ah[t][2] = *reinterpret_cast<const uint32_t*>(&sAh[r0 + 8]);
                Ah[t][3] = *reinterpret_cast<const uint32_t*>(&sAh[r1 + 8]);
                Al[t][0] = *reinterpret_cast<const uint32_t*>(&sAl[r0]);
                Al[t][1] = *reinterpret_cast<const uint32_t*>(&sAl[r1]);
                Al[t][2] = *reinterpret_cast<const uint32_t*>(&sAl[r0 + 8]);
                Al[t][3] = *reinterpret_cast<const uint32_t*>(&sAl[r1 + 8]);
            }
            uint32_t Bh[4][2], Bl[4][2];
            #pragma unroll
            for (int j = 0; j < 4; j++) {
                const int rb = (warp_n * 32 + j * 8 + g) * LDSK + kb + q * 2;
                Bh[j][0] = *reinterpret_cast<const uint32_t*>(&sBh[rb]);
                Bh[j][1] = *reinterpret_cast<const uint32_t*>(&sBh[rb + 8]);
                Bl[j][0] = *reinterpret_cast<const uint32_t*>(&sBl[rb]);
                Bl[j][1] = *reinterpret_cast<const uint32_t*>(&sBl[rb + 8]);
            }
            #pragma unroll
            for (int t = 0; t < 2; t++)
                #pragma unroll
                for (int j = 0; j < 4; j++) {
                    float* d = acc[t * 4 + j];
                    MMA_BF16(d, Ah[t], Bh[j]);   // hi*hi
                    MMA_BF16(d, Ah[t], Bl[j]);   // hi*lo
                    MMA_BF16(d, Al[t], Bh[j]);   // lo*hi
                }
        }
        __syncthreads();
    }

    // store fp16: c0,c1 -> row g; c2,c3 -> row g+8; cols 2q,2q+1
    #pragma unroll
    for (int t = 0; t < 2; t++) {
        const int row0 = block_row + warp_m * 32 + t * 16 + g;
        #pragma unroll
        for (int j = 0; j < 4; j++) {
            const int col = n0 + warp_n * 32 + j * 8 + q * 2;
            const float* d = acc[t * 4 + j];
            if (row0 < M)
                *reinterpret_cast<__half2*>(C + (size_t)row0 * ldc + col) =
                    __floats2half2_rn(d[0], d[1]);
            if (row0 + 8 < M)
                *reinterpret_cast<__half2*>(C + (size_t)(row0 + 8) * ldc + col) =
                    __floats2half2_rn(d[2], d[3]);
        }
    }
}

// ---------------- sparse aggregation (fp16 gather, fp32 accumulate) --------
// Out[i] = relu( bias + dinv[i]^2 * H[i] + sum_e w_e * H[src_e] )
// F/8 lanes per node; uint4 = 8 halves per lane; 4-edge unroll.
// TOUT = __half (layer 1) or float (layer 2 / d_out).
template <int F, typename TOUT>
__global__ __launch_bounds__(256)
void agg_kernel(const __half* __restrict__ H, const float* __restrict__ bias,
                TOUT* __restrict__ Out) {
    const int lanes = F / 8;                 // 32 (F=256) or 16 (F=128)
    const int tid = threadIdx.x;
    const int node = blockIdx.x * (256 / lanes) + tid / lanes;
    if (node >= N_NODES) return;
    const int f = (tid % lanes) * 8;

    const float di = g_dinv[node];
    const float w0 = di * di;

    float acc[8];
    {
        uint4 hv = *reinterpret_cast<const uint4*>(H + (size_t)node * F + f);
        const __half2* hp = reinterpret_cast<const __half2*>(&hv);
        #pragma unroll
        for (int j = 0; j < 4; j++) {
            float2 v = __half22float2(hp[j]);
            acc[j * 2 + 0] = fmaf(w0, v.x, bias[f + j * 2 + 0]);
            acc[j * 2 + 1] = fmaf(w0, v.y, bias[f + j * 2 + 1]);
        }
    }
    float acc1[8], acc2[8], acc3[8];
    #pragma unroll
    for (int j = 0; j < 8; j++) { acc1[j] = 0.f; acc2[j] = 0.f; acc3[j] = 0.f; }

    int e = g_rowstart[node];
    const int end = g_rowstart[node + 1];

    for (; e + 4 <= end; e += 4) {
        int   s0 = __ldg(&g_csr_src[e + 0]);
        int   s1 = __ldg(&g_csr_src[e + 1]);
        int   s2 = __ldg(&g_csr_src[e + 2]);
        int   s3 = __ldg(&g_csr_src[e + 3]);
        float w0e = __ldg(&g_csr_w[e + 0]);
        float w1e = __ldg(&g_csr_w[e + 1]);
        float w2e = __ldg(&g_csr_w[e + 2]);
        float w3e = __ldg(&g_csr_w[e + 3]);
        uint4 v0 = *reinterpret_cast<const uint4*>(H + (size_t)s0 * F + f);
        uint4 v1 = *reinterpret_cast<const uint4*>(H + (size_t)s1 * F + f);
        uint4 v2 = *reinterpret_cast<const uint4*>(H + (size_t)s2 * F + f);
        uint4 v3 = *reinterpret_cast<const uint4*>(H + (size_t)s3 * F + f);
        const __half2* p0 = reinterpret_cast<const __half2*>(&v0);
        const __half2* p1 = reinterpret_cast<const __half2*>(&v1);
        const __half2* p2 = reinterpret_cast<const __half2*>(&v2);
        const __half2* p3 = reinterpret_cast<const __half2*>(&v3);
        #pragma unroll
        for (int j = 0; j < 4; j++) {
            float2 f0 = __half22float2(p0[j]);
            float2 f1 = __half22float2(p1[j]);
            float2 f2 = __half22float2(p2[j]);
            float2 f3 = __half22float2(p3[j]);
            acc[j*2+0]  = fmaf(w0e, f0.x, acc[j*2+0]);
            acc[j*2+1]  = fmaf(w0e, f0.y, acc[j*2+1]);
            acc1[j*2+0] = fmaf(w1e, f1.x, acc1[j*2+0]);
            acc1[j*2+1] = fmaf(w1e, f1.y, acc1[j*2+1]);
            acc2[j*2+0] = fmaf(w2e, f2.x, acc2[j*2+0]);
            acc2[j*2+1] = fmaf(w2e, f2.y, acc2[j*2+1]);
            acc3[j*2+0] = fmaf(w3e, f3.x, acc3[j*2+0]);
            acc3[j*2+1] = fmaf(w3e, f3.y, acc3[j*2+1]);
        }
    }
    for (; e < end; e++) {
        int   s = __ldg(&g_csr_src[e]);
        float w = __ldg(&g_csr_w[e]);
        uint4 v = *reinterpret_cast<const uint4*>(H + (size_t)s * F + f);
        const __half2* p = reinterpret_cast<const __half2*>(&v);
        #pragma unroll
        for (int j = 0; j < 4; j++) {
            float2 fv = __half22float2(p[j]);
            acc[j*2+0] = fmaf(w, fv.x, acc[j*2+0]);
            acc[j*2+1] = fmaf(w, fv.y, acc[j*2+1]);
        }
    }

    float r[8];
    #pragma unroll
    for (int j = 0; j < 8; j++)
        r[j] = fmaxf((acc[j] + acc1[j]) + (acc2[j] + acc3[j]), 0.0f);

    if constexpr (sizeof(TOUT) == 2) {
        __half2 hr[4];
        #pragma unroll
        for (int j = 0; j < 4; j++)
            hr[j] = __floats2half2_rn(r[j * 2], r[j * 2 + 1]);
        *reinterpret_cast<uint4*>((__half*)Out + (size_t)node * F + f) =
            *reinterpret_cast<const uint4*>(hr);
    } else {
        float* dst = (float*)Out + (size_t)node * F + f;
        *reinterpret_cast<float4*>(dst)     = make_float4(r[0], r[1], r[2], r[3]);
        *reinterpret_cast<float4*>(dst + 4) = make_float4(r[4], r[5], r[6], r[7]);
    }
}

// ---------------- launcher ---------------------------------------------------

extern "C" void kernel_launch(void* const* d_in, const int* in_sizes, int n_in,
                              void* d_out, int out_size) {
    const float* x  = (const float*)d_in[0];
    const int*   ei = (const int*)d_in[1];
    const float* W1 = (const float*)d_in[2];
    const float* b1 = (const float*)d_in[3];
    const float* W2 = (const float*)d_in[4];
    const float* b2 = (const float*)d_in[5];
    float* out = (float*)d_out;

    const int E = in_sizes[1] / 2;
    const int* src = ei;
    const int* dst = ei + E;

    __half *h1p = nullptr, *h2p = nullptr, *a1p = nullptr;
    __nv_bfloat16 *w1thi = nullptr, *w1tlo = nullptr;
    __nv_bfloat16 *w2thi = nullptr, *w2tlo = nullptr;
    cudaGetSymbolAddress((void**)&h1p, g_h1);
    cudaGetSymbolAddress((void**)&h2p, g_h2);
    cudaGetSymbolAddress((void**)&a1p, g_a1);
    cudaGetSymbolAddress((void**)&w1thi, g_w1t_hi);
    cudaGetSymbolAddress((void**)&w1tlo, g_w1t_lo);
    cudaGetSymbolAddress((void**)&w2thi, g_w2t_hi);
    cudaGetSymbolAddress((void**)&w2tlo, g_w2t_lo);

    // lazily-created side stream + events (host-side objects; created once,
    // reused every call -> identical captured graph each time)
    static cudaStream_t sB = nullptr;
    static cudaEvent_t evFork = nullptr, evJoin = nullptr;
    if (sB == nullptr) {
        cudaStreamCreateWithFlags(&sB, cudaStreamNonBlocking);
        cudaEventCreateWithFlags(&evFork, cudaEventDisableTiming);
        cudaEventCreateWithFlags(&evJoin, cudaEventDisableTiming);
    }

    const int TB = 256;
    const int MT = (N_NODES + 127) / 128;   // 782

    // ---- fork: side stream B inherits current state of the main stream ----
    cudaEventRecord(evFork, 0);
    cudaStreamWaitEvent(sB, evFork, 0);

    // stream B: CSR build chain + W2 conversion (independent of GEMM1)
    init_kernel<<<(N_NODES + TB - 1) / TB, TB, 0, sB>>>();
    count_kernel<<<(E + TB - 1) / TB, TB, 0, sB>>>(dst, E);
    dinv_kernel<<<(N_NODES + TB - 1) / TB, TB, 0, sB>>>();
    scan_partial_kernel<<<SCAN_BLOCKS, 256, 0, sB>>>();
    scan_top_kernel<<<1, 128, 0, sB>>>();
    scan_final_kernel<<<SCAN_BLOCKS, 256, 0, sB>>>();
    fill_kernel<<<(E + TB - 1) / TB, TB, 0, sB>>>(src, dst, E);
    convert_w_kernel<<<(F_OUT * K_TOT + TB - 1) / TB, TB, 0, sB>>>(
        W2, w2thi, w2tlo, K_TOT, F_OUT);
    cudaEventRecord(evJoin, sB);

    // main stream: W1 conversion + GEMM1 (needs only x, W1)
    convert_w_kernel<<<(F_HID * K_TOT + TB - 1) / TB, TB>>>(
        W1, w1thi, w1tlo, K_TOT, F_HID);
    dim3 g1(MT, F_HID / 64);
    mma_gemm_kernel<float><<<g1, 256>>>(x, w1thi, w1tlo, h1p, N_NODES, F_HID);

    // ---- join: main stream waits for CSR chain before aggregation ----
    cudaStreamWaitEvent(0, evJoin, 0);

    // layer 1 aggregation (fp16 out), layer 2 GEMM + aggregation
    agg_kernel<F_HID, __half><<<(N_NODES * (F_HID / 8) + 255) / 256, 256>>>(
        h1p, b1, a1p);
    dim3 g2(MT, F_OUT / 64);
    mma_gemm_kernel<__half><<<g2, 256>>>(a1p, w2thi, w2tlo, h2p, N_NODES, F_OUT);
    agg_kernel<F_OUT, float><<<(N_NODES * (F_OUT / 8) + 255) / 256, 256>>>(
        h2p, b2, out);
}

// round 12
// speedup vs baseline: 1.3825x; 1.1859x over previous
#include <cuda_runtime.h>
#include <cuda_bf16.h>
#include <cuda_fp16.h>
#include <cstdint>
#include <math.h>

// ---------------- problem constants ----------------------------------------
#define N_NODES 100000
#define N_EDGES 1600000
#define F_IN    256
#define F_HID   256
#define F_OUT   128
#define K_TOT   256          // K dim for both GEMMs

#define SCAN_CHUNK  1024
#define SCAN_BLOCKS ((N_NODES + SCAN_CHUNK - 1) / SCAN_CHUNK)   // 98

// ---------------- device scratch (static, no allocations) ------------------
__device__ int   g_deg[N_NODES];
__device__ float g_dinv[N_NODES];
__device__ int   g_rowstart[N_NODES + 1];
__device__ int   g_cursor[N_NODES];
__device__ int   g_partial[SCAN_BLOCKS];
__device__ int   g_csr_src[N_EDGES];
__device__ float g_csr_w[N_EDGES];

__device__ __half g_w1t[F_HID * K_TOT];     // [256][256] = W1^T (fp16)
__device__ __half g_w2t[F_OUT * K_TOT];     // [128][256] = W2^T (fp16)
__device__ __half g_h1[(size_t)N_NODES * F_HID];       // x @ W1 (fp16)
__device__ __half g_a1[(size_t)N_NODES * F_HID];       // relu(agg(h1)+b1) fp16
__device__ __half g_h2[(size_t)N_NODES * F_OUT];       // a1 @ W2 (fp16)

// ---------------- CSR construction -----------------------------------------

__global__ void init_kernel() {
    int i = blockIdx.x * blockDim.x + threadIdx.x;
    if (i < N_NODES) { g_deg[i] = 1; g_cursor[i] = 0; }
}

__global__ void count_kernel(const int* __restrict__ dst, int E) {
    int e = blockIdx.x * blockDim.x + threadIdx.x;
    if (e < E) atomicAdd(&g_deg[dst[e]], 1);
}

__global__ void dinv_kernel() {
    int i = blockIdx.x * blockDim.x + threadIdx.x;
    if (i < N_NODES) g_dinv[i] = rsqrtf((float)g_deg[i]);
}

__global__ __launch_bounds__(256) void scan_partial_kernel() {
    __shared__ int red[256];
    const int base = blockIdx.x * SCAN_CHUNK;
    int s = 0;
    for (int j = threadIdx.x; j < SCAN_CHUNK; j += 256) {
        int idx = base + j;
        if (idx < N_NODES) s += g_deg[idx] - 1;
    }
    red[threadIdx.x] = s;
    __syncthreads();
    #pragma unroll
    for (int off = 128; off > 0; off >>= 1) {
        if (threadIdx.x < off) red[threadIdx.x] += red[threadIdx.x + off];
        __syncthreads();
    }
    if (threadIdx.x == 0) g_partial[blockIdx.x] = red[0];
}

__global__ void scan_top_kernel() {
    __shared__ int sh[SCAN_BLOCKS];
    for (int i = threadIdx.x; i < SCAN_BLOCKS; i += blockDim.x) sh[i] = g_partial[i];
    __syncthreads();
    if (threadIdx.x == 0) {
        int run = 0;
        for (int i = 0; i < SCAN_BLOCKS; i++) { int v = sh[i]; sh[i] = run; run += v; }
        g_rowstart[N_NODES] = run;
    }
    __syncthreads();
    for (int i = threadIdx.x; i < SCAN_BLOCKS; i += blockDim.x) g_partial[i] = sh[i];
}

__global__ __launch_bounds__(256) void scan_final_kernel() {
    __shared__ int sh[256];
    const int t = threadIdx.x;
    const int idx0 = blockIdx.x * SCAN_CHUNK + t * 4;
    int v[4]; int s = 0;
    #pragma unroll
    for (int j = 0; j < 4; j++) {
        int idx = idx0 + j;
        int d = (idx < N_NODES) ? (g_deg[idx] - 1) : 0;
        v[j] = s; s += d;
    }
    sh[t] = s;
    __syncthreads();
    #pragma unroll
    for (int off = 1; off < 256; off <<= 1) {
        int val = (t >= off) ? sh[t - off] : 0;
        __syncthreads();
        sh[t] += val;
        __syncthreads();
    }
    int excl = ((t == 0) ? 0 : sh[t - 1]) + g_partial[blockIdx.x];
    #pragma unroll
    for (int j = 0; j < 4; j++) {
        int idx = idx0 + j;
        if (idx < N_NODES) g_rowstart[idx] = excl + v[j];
    }
}

__global__ void fill_kernel(const int* __restrict__ src,
                            const int* __restrict__ dst, int E) {
    int e = blockIdx.x * blockDim.x + threadIdx.x;
    if (e < E) {
        int d = dst[e];
        int s = src[e];
        int pos = atomicAdd(&g_cursor[d], 1);
        int idx = g_rowstart[d] + pos;
        g_csr_src[idx] = s;
        g_csr_w[idx]   = g_dinv[s] * g_dinv[d];
    }
}

// ---------------- weight conversion: W [K][N] -> WT fp16 [N][K] -------------

__global__ void convert_w_kernel(const float* __restrict__ W,
                                 __half* __restrict__ WT, int K, int N) {
    int i = blockIdx.x * blockDim.x + threadIdx.x;
    if (i >= N * K) return;
    int nrow = i / K;
    int k = i - nrow * K;
    WT[i] = __float2half(W[(size_t)k * N + nrow]);
}

// ---------------- mma.sync fp16 GEMM ----------------------------------------
// C[M rows, 64-col slice](fp16) = A[M,256] @ B^T, B fp16 [N][K].
// A (fp32 or fp16) converted to fp16 in registers while staging to smem.
// CTA tile 128x64, 8 warps (4 m x 2 n), warp tile 32x32, fp32 accumulate.

#define LDSK 40   // fp16 elements per smem row (32 data + 8 pad); 80B, 16B-mult

#define MMA_F16(d, a, b) \
    asm volatile("mma.sync.aligned.m16n8k16.row.col.f32.f16.f16.f32 " \
        "{%0,%1,%2,%3}, {%4,%5,%6,%7}, {%8,%9}, {%0,%1,%2,%3};" \
        : "+f"((d)[0]), "+f"((d)[1]), "+f"((d)[2]), "+f"((d)[3]) \
        : "r"((a)[0]), "r"((a)[1]), "r"((a)[2]), "r"((a)[3]), \
          "r"((b)[0]), "r"((b)[1]))

template <typename TA>
__global__ __launch_bounds__(256)
void mma_gemm_kernel(const TA* __restrict__ A,
                     const __half* __restrict__ B,
                     __half* __restrict__ C, int M, int ldc) {
    __shared__ __align__(16) __half sA[128 * LDSK];
    __shared__ __align__(16) __half sB[64 * LDSK];

    const int tid  = threadIdx.x;
    const int wid  = tid >> 5;
    const int lane = tid & 31;
    const int warp_m = wid & 3;        // 0..3 -> m offset 32*warp_m
    const int warp_n = wid >> 2;       // 0..1 -> n offset 32*warp_n
    const int block_row = blockIdx.x * 128;
    const int n0 = blockIdx.y * 64;

    const int g = lane >> 2;           // 0..7
    const int q = lane & 3;            // 0..3

    float acc[8][4];
    #pragma unroll
    for (int i = 0; i < 8; i++)
        #pragma unroll
        for (int j = 0; j < 4; j++) acc[i][j] = 0.0f;

    for (int c = 0; c < 8; c++) {
        const int k0 = c * 32;

        if constexpr (sizeof(TA) == 4) {
            // fp32 A: 128 rows x 8 float4 = 1024; convert to fp16 in regs.
            #pragma unroll
            for (int t = tid; t < 1024; t += 256) {
                const int row = t >> 3;
                const int u   = t & 7;        // float4 index within row
                const int grow = block_row + row;
                float4 v = make_float4(0.f, 0.f, 0.f, 0.f);
                if (grow < M)
                    v = *reinterpret_cast<const float4*>(
                        (const float*)A + (size_t)grow * K_TOT + k0 + u * 4);
                __half2* d = reinterpret_cast<__half2*>(
                    sA + row * LDSK + u * 4);
                d[0] = __floats2half2_rn(v.x, v.y);
                d[1] = __floats2half2_rn(v.z, v.w);
            }
        } else {
            // fp16 A: 128 rows x 4 uint4 (8 halves each) = 512; direct copy.
            #pragma unroll
            for (int t = tid; t < 512; t += 256) {
                const int row = t >> 2;
                const int u   = t & 3;        // uint4 index within row
                const int grow = block_row + row;
                uint4 hv = make_uint4(0u, 0u, 0u, 0u);
                if (grow < M)
                    hv = *reinterpret_cast<const uint4*>(
                        (const __half*)A + (size_t)grow * K_TOT + k0 + u * 8);
                *reinterpret_cast<uint4*>(sA + row * LDSK + u * 8) = hv;
            }
        }
        // B chunk: 64 rows x 4 uint4 each => 256 uint4
        #pragma unroll
        for (int t = tid; t < 256; t += 256) {
            const int row = t >> 2;
            const int u   = t & 3;
            uint4 v = *reinterpret_cast<const uint4*>(
                B + (size_t)(n0 + row) * K_TOT + k0 + u * 8);
            *reinterpret_cast<uint4*>(sB + row * LDSK + u * 8) = v;
        }
        __syncthreads();

        #pragma unroll
        for (int kk = 0; kk < 2; kk++) {
            const int kb = kk * 16;
            uint32_t Af[2][4];
            #pragma unroll
            for (int t = 0; t < 2; t++) {
                const int r0 = (warp_m * 32 + t * 16 + g) * LDSK + kb + q * 2;
                const int r1 = r0 + 8 * LDSK;
                Af[t][0] = *reinterpret_cast<const uint32_t*>(&sA[r0]);
                Af[t][1] = *reinterpret_cast<const uint32_t*>(&sA[r1]);
                Af[t][2] = *reinterpret_cast<const uint32_t*>(&sA[r0 + 8]);
                Af[t][3] = *reinterpret_cast<const uint32_t*>(&sA[r1 + 8]);
            }
            uint32_t Bf[4][2];
            #pragma unroll
            for (int j = 0; j < 4; j++) {
                const int rb = (warp_n * 32 + j * 8 + g) * LDSK + kb + q * 2;
                Bf[j][0] = *reinterpret_cast<const uint32_t*>(&sB[rb]);
                Bf[j][1] = *reinterpret_cast<const uint32_t*>(&sB[rb + 8]);
            }
            #pragma unroll
            for (int t = 0; t < 2; t++)
                #pragma unroll
                for (int j = 0; j < 4; j++)
                    MMA_F16(acc[t * 4 + j], Af[t], Bf[j]);
        }
        __syncthreads();
    }

    // store fp16: c0,c1 -> row g; c2,c3 -> row g+8; cols 2q,2q+1
    #pragma unroll
    for (int t = 0; t < 2; t++) {
        const int row0 = block_row + warp_m * 32 + t * 16 + g;
        #pragma unroll
        for (int j = 0; j < 4; j++) {
            const int col = n0 + warp_n * 32 + j * 8 + q * 2;
            const float* d = acc[t * 4 + j];
            if (row0 < M)
                *reinterpret_cast<__half2*>(C + (size_t)row0 * ldc + col) =
                    __floats2half2_rn(d[0], d[1]);
            if (row0 + 8 < M)
                *reinterpret_cast<__half2*>(C + (size_t)(row0 + 8) * ldc + col) =
                    __floats2half2_rn(d[2], d[3]);
        }
    }
}

// ---------------- sparse aggregation (fp16 gather, fp32 accumulate) --------
// Out[i] = relu( bias + dinv[i]^2 * H[i] + sum_e w_e * H[src_e] )
// F/8 lanes per node; uint4 = 8 halves per lane; 4-edge unroll.
// TOUT = __half (layer 1) or float (layer 2 / d_out).
template <int F, typename TOUT>
__global__ __launch_bounds__(256)
void agg_kernel(const __half* __restrict__ H, const float* __restrict__ bias,
                TOUT* __restrict__ Out) {
    const int lanes = F / 8;                 // 32 (F=256) or 16 (F=128)
    const int tid = threadIdx.x;
    const int node = blockIdx.x * (256 / lanes) + tid / lanes;
    if (node >= N_NODES) return;
    const int f = (tid % lanes) * 8;

    const float di = g_dinv[node];
    const float w0 = di * di;

    float acc[8];
    {
        uint4 hv = *reinterpret_cast<const uint4*>(H + (size_t)node * F + f);
        const __half2* hp = reinterpret_cast<const __half2*>(&hv);
        #pragma unroll
        for (int j = 0; j < 4; j++) {
            float2 v = __half22float2(hp[j]);
            acc[j * 2 + 0] = fmaf(w0, v.x, bias[f + j * 2 + 0]);
            acc[j * 2 + 1] = fmaf(w0, v.y, bias[f + j * 2 + 1]);
        }
    }
    float acc1[8], acc2[8], acc3[8];
    #pragma unroll
    for (int j = 0; j < 8; j++) { acc1[j] = 0.f; acc2[j] = 0.f; acc3[j] = 0.f; }

    int e = g_rowstart[node];
    const int end = g_rowstart[node + 1];

    for (; e + 4 <= end; e += 4) {
        int   s0 = __ldg(&g_csr_src[e + 0]);
        int   s1 = __ldg(&g_csr_src[e + 1]);
        int   s2 = __ldg(&g_csr_src[e + 2]);
        int   s3 = __ldg(&g_csr_src[e + 3]);
        float w0e = __ldg(&g_csr_w[e + 0]);
        float w1e = __ldg(&g_csr_w[e + 1]);
        float w2e = __ldg(&g_csr_w[e + 2]);
        float w3e = __ldg(&g_csr_w[e + 3]);
        uint4 v0 = *reinterpret_cast<const uint4*>(H + (size_t)s0 * F + f);
        uint4 v1 = *reinterpret_cast<const uint4*>(H + (size_t)s1 * F + f);
        uint4 v2 = *reinterpret_cast<const uint4*>(H + (size_t)s2 * F + f);
        uint4 v3 = *reinterpret_cast<const uint4*>(H + (size_t)s3 * F + f);
        const __half2* p0 = reinterpret_cast<const __half2*>(&v0);
        const __half2* p1 = reinterpret_cast<const __half2*>(&v1);
        const __half2* p2 = reinterpret_cast<const __half2*>(&v2);
        const __half2* p3 = reinterpret_cast<const __half2*>(&v3);
        #pragma unroll
        for (int j = 0; j < 4; j++) {
            float2 f0 = __half22float2(p0[j]);
            float2 f1 = __half22float2(p1[j]);
            float2 f2 = __half22float2(p2[j]);
            float2 f3 = __half22float2(p3[j]);
            acc[j*2+0]  = fmaf(w0e, f0.x, acc[j*2+0]);
            acc[j*2+1]  = fmaf(w0e, f0.y, acc[j*2+1]);
            acc1[j*2+0] = fmaf(w1e, f1.x, acc1[j*2+0]);
            acc1[j*2+1] = fmaf(w1e, f1.y, acc1[j*2+1]);
            acc2[j*2+0] = fmaf(w2e, f2.x, acc2[j*2+0]);
            acc2[j*2+1] = fmaf(w2e, f2.y, acc2[j*2+1]);
            acc3[j*2+0] = fmaf(w3e, f3.x, acc3[j*2+0]);
            acc3[j*2+1] = fmaf(w3e, f3.y, acc3[j*2+1]);
        }
    }
    for (; e < end; e++) {
        int   s = __ldg(&g_csr_src[e]);
        float w = __ldg(&g_csr_w[e]);
        uint4 v = *reinterpret_cast<const uint4*>(H + (size_t)s * F + f);
        const __half2* p = reinterpret_cast<const __half2*>(&v);
        #pragma unroll
        for (int j = 0; j < 4; j++) {
            float2 fv = __half22float2(p[j]);
            acc[j*2+0] = fmaf(w, fv.x, acc[j*2+0]);
            acc[j*2+1] = fmaf(w, fv.y, acc[j*2+1]);
        }
    }

    float r[8];
    #pragma unroll
    for (int j = 0; j < 8; j++)
        r[j] = fmaxf((acc[j] + acc1[j]) + (acc2[j] + acc3[j]), 0.0f);

    if constexpr (sizeof(TOUT) == 2) {
        __half2 hr[4];
        #pragma unroll
        for (int j = 0; j < 4; j++)
            hr[j] = __floats2half2_rn(r[j * 2], r[j * 2 + 1]);
        *reinterpret_cast<uint4*>((__half*)Out + (size_t)node * F + f) =
            *reinterpret_cast<const uint4*>(hr);
    } else {
        float* dst = (float*)Out + (size_t)node * F + f;
        *reinterpret_cast<float4*>(dst)     = make_float4(r[0], r[1], r[2], r[3]);
        *reinterpret_cast<float4*>(dst + 4) = make_float4(r[4], r[5], r[6], r[7]);
    }
}

// ---------------- launcher ---------------------------------------------------

extern "C" void kernel_launch(void* const* d_in, const int* in_sizes, int n_in,
                              void* d_out, int out_size) {
    const float* x  = (const float*)d_in[0];
    const int*   ei = (const int*)d_in[1];
    const float* W1 = (const float*)d_in[2];
    const float* b1 = (const float*)d_in[3];
    const float* W2 = (const float*)d_in[4];
    const float* b2 = (const float*)d_in[5];
    float* out = (float*)d_out;

    const int E = in_sizes[1] / 2;
    const int* src = ei;
    const int* dst = ei + E;

    __half *h1p = nullptr, *h2p = nullptr, *a1p = nullptr;
    __half *w1t = nullptr, *w2t = nullptr;
    cudaGetSymbolAddress((void**)&h1p, g_h1);
    cudaGetSymbolAddress((void**)&h2p, g_h2);
    cudaGetSymbolAddress((void**)&a1p, g_a1);
    cudaGetSymbolAddress((void**)&w1t, g_w1t);
    cudaGetSymbolAddress((void**)&w2t, g_w2t);

    // lazily-created side stream + events (host-side objects; created once,
    // reused every call -> identical captured graph each time)
    static cudaStream_t sB = nullptr;
    static cudaEvent_t evFork = nullptr, evJoin = nullptr;
    if (sB == nullptr) {
        cudaStreamCreateWithFlags(&sB, cudaStreamNonBlocking);
        cudaEventCreateWithFlags(&evFork, cudaEventDisableTiming);
        cudaEventCreateWithFlags(&evJoin, cudaEventDisableTiming);
    }

    const int TB = 256;
    const int MT = (N_NODES + 127) / 128;   // 782

    // ---- fork: side stream B inherits current state of the main stream ----
    cudaEventRecord(evFork, 0);
    cudaStreamWaitEvent(sB, evFork, 0);

    // stream B: CSR build chain + W2 conversion (independent of GEMM1)
    init_kernel<<<(N_NODES + TB - 1) / TB, TB, 0, sB>>>();
    count_kernel<<<(E + TB - 1) / TB, TB, 0, sB>>>(dst, E);
    dinv_kernel<<<(N_NODES + TB - 1) / TB, TB, 0, sB>>>();
    scan_partial_kernel<<<SCAN_BLOCKS, 256, 0, sB>>>();
    scan_top_kernel<<<1, 128, 0, sB>>>();
    scan_final_kernel<<<SCAN_BLOCKS, 256, 0, sB>>>();
    fill_kernel<<<(E + TB - 1) / TB, TB, 0, sB>>>(src, dst, E);
    convert_w_kernel<<<(F_OUT * K_TOT + TB - 1) / TB, TB, 0, sB>>>(
        W2, w2t, K_TOT, F_OUT);
    cudaEventRecord(evJoin, sB);

    // main stream: W1 conversion + GEMM1 (needs only x, W1)
    convert_w_kernel<<<(F_HID * K_TOT + TB - 1) / TB, TB>>>(
        W1, w1t, K_TOT, F_HID);
    dim3 g1(MT, F_HID / 64);
    mma_gemm_kernel<float><<<g1, 256>>>(x, w1t, h1p, N_NODES, F_HID);

    // ---- join: main stream waits for CSR chain before aggregation ----
    cudaStreamWaitEvent(0, evJoin, 0);

    // layer 1 aggregation (fp16 out), layer 2 GEMM + aggregation
    agg_kernel<F_HID, __half><<<(N_NODES * (F_HID / 8) + 255) / 256, 256>>>(
        h1p, b1, a1p);
    dim3 g2(MT, F_OUT / 64);
    mma_gemm_kernel<__half><<<g2, 256>>>(a1p, w2t, h2p, N_NODES, F_OUT);
    agg_kernel<F_OUT, float><<<(N_NODES * (F_OUT / 8) + 255) / 256, 256>>>(
        h2p, b2, out);
}